// round 15
// baseline (speedup 1.0000x reference)
#include <cuda_runtime.h>
#include <cuda_bf16.h>
#include <cstdint>

#define N_NODES 100000
#define E_EDGES 800000
#define HIDF 128
#define OUTF 40
#define BN_EPS 1e-5f
#define WPR 64          // bf16x2 words per feature row (128 bf16)

// ---------------- scratch ----------------
__device__ unsigned g_meanh[(size_t)N_NODES * WPR];
__device__ unsigned g_meanl[(size_t)N_NODES * WPR];
__device__ float g_h0 [(size_t)N_NODES * HIDF];
__device__ float g_h1 [(size_t)N_NODES * HIDF];
__device__ int   g_rowptr[N_NODES + 1];
__device__ int   g_cursor[N_NODES];
__device__ int   g_csr[E_EDGES];
__device__ int   g_bsum[1024];
__device__ float g_sums[512];
__device__ float g_bnp0[256];
__device__ float g_bnp1[256];
#define WOFF_L0 0
#define WOFF_R0 8192
#define WOFF_L1 16384
#define WOFF_R1 24576
#define WOFF_L2 32768
#define WOFF_R2 35328
#define WTOT    37888
__device__ unsigned g_wh[WTOT];
__device__ unsigned g_wl[WTOT];

// ---------------- helpers ----------------
__device__ __forceinline__ unsigned pack_bf16x2(float lo, float hi) {
    unsigned r;
    asm("cvt.rn.bf16x2.f32 %0, %1, %2;" : "=r"(r) : "f"(hi), "f"(lo));
    return r;
}
__device__ __forceinline__ float bf_lo(unsigned u) { return __uint_as_float(u << 16); }
__device__ __forceinline__ float bf_hi(unsigned u) { return __uint_as_float(u & 0xffff0000u); }

__device__ __forceinline__ void split4(float4 v, unsigned* h, unsigned* l) {
    h[0] = pack_bf16x2(v.x, v.y);
    h[1] = pack_bf16x2(v.z, v.w);
    l[0] = pack_bf16x2(v.x - bf_lo(h[0]), v.y - bf_hi(h[0]));
    l[1] = pack_bf16x2(v.z - bf_lo(h[1]), v.w - bf_hi(h[1]));
}

#define MMA_BF16(d, A0,A1,A2,A3, B0,B1) \
    asm volatile("mma.sync.aligned.m16n8k16.row.col.f32.bf16.bf16.f32 " \
        "{%0,%1,%2,%3}, {%4,%5,%6,%7}, {%8,%9}, {%0,%1,%2,%3};" \
        : "+f"((d)[0]), "+f"((d)[1]), "+f"((d)[2]), "+f"((d)[3]) \
        : "r"(A0), "r"(A1), "r"(A2), "r"(A3), "r"(B0), "r"(B1))

__device__ __forceinline__ void ldsm_x4(unsigned* r, unsigned addr) {
    asm volatile("ldmatrix.sync.aligned.m8n8.x4.shared.b16 {%0,%1,%2,%3}, [%4];"
                 : "=r"(r[0]), "=r"(r[1]), "=r"(r[2]), "=r"(r[3]) : "r"(addr));
}

__device__ __forceinline__ void redg_f32(float* p, float v) {
    asm volatile("red.global.add.f32 [%0], %1;" :: "l"(p), "f"(v) : "memory");
}

// ---------------- small utils ----------------
__global__ void zero_int_kernel(int* __restrict__ p, int n) {
    int i = blockIdx.x * blockDim.x + threadIdx.x;
    if (i < n) p[i] = 0;
}
__global__ void zero_f_kernel(float* __restrict__ p, int n) {
    int i = blockIdx.x * blockDim.x + threadIdx.x;
    if (i < n) p[i] = 0.0f;
}

// ---------------- weight pre-split ----------------
__global__ void splitw_kernel(const float* __restrict__ Wl0, const float* __restrict__ Wr0,
                              const float* __restrict__ Wl1, const float* __restrict__ Wr1,
                              const float* __restrict__ Wl2, const float* __restrict__ Wr2,
                              unsigned* __restrict__ wh, unsigned* __restrict__ wl) {
    int i = blockIdx.x * blockDim.x + threadIdx.x;
    if (i >= WTOT) return;
    const float* src; int idx, NC;
    if      (i < WOFF_R0) { src = Wl0; idx = i;            NC = 128; }
    else if (i < WOFF_L1) { src = Wr0; idx = i - WOFF_R0;  NC = 128; }
    else if (i < WOFF_R1) { src = Wl1; idx = i - WOFF_L1;  NC = 128; }
    else if (i < WOFF_L2) { src = Wr1; idx = i - WOFF_R1;  NC = 128; }
    else if (i < WOFF_R2) { src = Wl2; idx = i - WOFF_L2;  NC = OUTF; }
    else                  { src = Wr2; idx = i - WOFF_R2;  NC = OUTF; }
    int n = idx >> 6, kw = idx & 63;
    float v0 = src[(size_t)(2*kw)     * NC + n];
    float v1 = src[(size_t)(2*kw + 1) * NC + n];
    unsigned h = pack_bf16x2(v0, v1);
    unsigned l = pack_bf16x2(v0 - bf_lo(h), v1 - bf_hi(h));
    wh[i] = h; wl[i] = l;
}

// ---------------- CSR build ----------------
__global__ void degree_kernel(const int* __restrict__ ei, int* __restrict__ rowptr,
                              int E, int N) {
    int e = blockIdx.x * blockDim.x + threadIdx.x;
    if (e >= E) return;
    int s = ei[e], d = ei[E + e];
    if ((unsigned)s < (unsigned)N && (unsigned)d < (unsigned)N)
        atomicAdd(&rowptr[d + 1], 1);
}

__global__ void scan1_kernel(int* __restrict__ data, int* __restrict__ bsum, int n) {
    __shared__ int sh[1024];
    int gid = blockIdx.x * 1024 + threadIdx.x;
    int v = (gid < n) ? data[gid] : 0;
    sh[threadIdx.x] = v;
    __syncthreads();
    #pragma unroll
    for (int off = 1; off < 1024; off <<= 1) {
        int t = (threadIdx.x >= off) ? sh[threadIdx.x - off] : 0;
        __syncthreads();
        sh[threadIdx.x] += t;
        __syncthreads();
    }
    if (gid < n) data[gid] = sh[threadIdx.x];
    if (threadIdx.x == 1023) bsum[blockIdx.x] = sh[1023];
}

__global__ void scan2_kernel(int* __restrict__ bsum, int nb) {
    __shared__ int sh[1024];
    int v = (threadIdx.x < nb) ? bsum[threadIdx.x] : 0;
    sh[threadIdx.x] = v;
    __syncthreads();
    #pragma unroll
    for (int off = 1; off < 1024; off <<= 1) {
        int t = (threadIdx.x >= off) ? sh[threadIdx.x - off] : 0;
        __syncthreads();
        sh[threadIdx.x] += t;
        __syncthreads();
    }
    if (threadIdx.x < nb) bsum[threadIdx.x] = sh[threadIdx.x];
}

__global__ void scan3_kernel(int* __restrict__ data, const int* __restrict__ bsum,
                             int* __restrict__ cursor, int n, int N) {
    int gid = blockIdx.x * 1024 + threadIdx.x;
    if (gid >= n) return;
    int add = (blockIdx.x > 0) ? bsum[blockIdx.x - 1] : 0;
    int v = data[gid] + add;
    data[gid] = v;
    if (gid < N) cursor[gid] = v;
}

__global__ void fill_kernel(const int* __restrict__ ei, int* __restrict__ cursor,
                            int* __restrict__ csr, int E, int N) {
    int e = blockIdx.x * blockDim.x + threadIdx.x;
    if (e >= E) return;
    int s = ei[e], d = ei[E + e];
    if ((unsigned)s >= (unsigned)N || (unsigned)d >= (unsigned)N) return;
    int pos = atomicAdd(&cursor[d], 1);
    csr[pos] = s;
}

// ---------------- gather-mean, writes split bf16 hi/lo words ----------------
__global__ void __launch_bounds__(256)
gather_kernel(const float* __restrict__ feat,
              const int* __restrict__ rowptr,
              const int* __restrict__ csr,
              const float* __restrict__ bnp,
              unsigned* __restrict__ meanh,
              unsigned* __restrict__ meanl, int N) {
    int node = blockIdx.x * 8 + (threadIdx.x >> 5);
    if (node >= N) return;
    int c = (threadIdx.x & 31) << 2;

    float4 sc = make_float4(1.f,1.f,1.f,1.f), sh = make_float4(0.f,0.f,0.f,0.f);
    bool bn = (bnp != nullptr);
    if (bn) {
        sc = *reinterpret_cast<const float4*>(bnp + c);
        sh = *reinterpret_cast<const float4*>(bnp + 128 + c);
    }

    int beg = rowptr[node], end = rowptr[node + 1];
    float4 acc = make_float4(0.f,0.f,0.f,0.f);
    int j = beg;
    for (; j + 4 <= end; j += 4) {
        int i0 = csr[j], i1 = csr[j+1], i2 = csr[j+2], i3 = csr[j+3];
        float4 v0 = *reinterpret_cast<const float4*>(feat + (size_t)i0 * HIDF + c);
        float4 v1 = *reinterpret_cast<const float4*>(feat + (size_t)i1 * HIDF + c);
        float4 v2 = *reinterpret_cast<const float4*>(feat + (size_t)i2 * HIDF + c);
        float4 v3 = *reinterpret_cast<const float4*>(feat + (size_t)i3 * HIDF + c);
        if (bn) {
            v0.x=fmaxf(fmaf(v0.x,sc.x,sh.x),0.f); v0.y=fmaxf(fmaf(v0.y,sc.y,sh.y),0.f);
            v0.z=fmaxf(fmaf(v0.z,sc.z,sh.z),0.f); v0.w=fmaxf(fmaf(v0.w,sc.w,sh.w),0.f);
            v1.x=fmaxf(fmaf(v1.x,sc.x,sh.x),0.f); v1.y=fmaxf(fmaf(v1.y,sc.y,sh.y),0.f);
            v1.z=fmaxf(fmaf(v1.z,sc.z,sh.z),0.f); v1.w=fmaxf(fmaf(v1.w,sc.w,sh.w),0.f);
            v2.x=fmaxf(fmaf(v2.x,sc.x,sh.x),0.f); v2.y=fmaxf(fmaf(v2.y,sc.y,sh.y),0.f);
            v2.z=fmaxf(fmaf(v2.z,sc.z,sh.z),0.f); v2.w=fmaxf(fmaf(v2.w,sc.w,sh.w),0.f);
            v3.x=fmaxf(fmaf(v3.x,sc.x,sh.x),0.f); v3.y=fmaxf(fmaf(v3.y,sc.y,sh.y),0.f);
            v3.z=fmaxf(fmaf(v3.z,sc.z,sh.z),0.f); v3.w=fmaxf(fmaf(v3.w,sc.w,sh.w),0.f);
        }
        acc.x += v0.x + v1.x + v2.x + v3.x;
        acc.y += v0.y + v1.y + v2.y + v3.y;
        acc.z += v0.z + v1.z + v2.z + v3.z;
        acc.w += v0.w + v1.w + v2.w + v3.w;
    }
    for (; j < end; j++) {
        int i0 = csr[j];
        float4 v0 = *reinterpret_cast<const float4*>(feat + (size_t)i0 * HIDF + c);
        if (bn) {
            v0.x=fmaxf(fmaf(v0.x,sc.x,sh.x),0.f); v0.y=fmaxf(fmaf(v0.y,sc.y,sh.y),0.f);
            v0.z=fmaxf(fmaf(v0.z,sc.z,sh.z),0.f); v0.w=fmaxf(fmaf(v0.w,sc.w,sh.w),0.f);
        }
        acc.x += v0.x; acc.y += v0.y; acc.z += v0.z; acc.w += v0.w;
    }
    float invd = (end > beg) ? 1.0f / (float)(end - beg) : 0.0f;
    acc.x *= invd; acc.y *= invd; acc.z *= invd; acc.w *= invd;
    unsigned h[2], l[2];
    split4(acc, h, l);
    size_t w = (size_t)node * WPR + (c >> 1);
    *reinterpret_cast<uint2*>(meanh + w) = make_uint2(h[0], h[1]);
    *reinterpret_cast<uint2*>(meanl + w) = make_uint2(l[0], l[1]);
}

// ======== bf16 3x-split TC GEMM, ldmatrix fragments, register-prefetch pipeline =====
#define SWH  20
#define SWBS 20

__global__ void __launch_bounds__(256, 2)
gemm_tc128_kernel(const unsigned* __restrict__ meanh,
                  const unsigned* __restrict__ meanl,
                  const float* __restrict__ feat,
                  const float* __restrict__ bnp,
                  const unsigned* __restrict__ whl, const unsigned* __restrict__ wll,
                  const unsigned* __restrict__ whr, const unsigned* __restrict__ wlr,
                  float* __restrict__ out,
                  float* __restrict__ stats,
                  int nrows) {
    __shared__ unsigned sAhi[128 * SWH];
    __shared__ unsigned sAlo[128 * SWH];
    __shared__ unsigned sBhi[128 * SWBS];
    __shared__ unsigned sBlo[128 * SWBS];
    __shared__ float    sBn[256];

    int tid  = threadIdx.x;
    int row0 = blockIdx.x * 128;
    int lane = tid & 31;
    int wid  = tid >> 5;
    int qr = lane >> 2, qc = lane & 3;
    int r0w = (wid & 3) * 32;
    int n0w = (wid >> 2) * 64;
    bool hasbn = (bnp != nullptr);

    if (hasbn && tid < 256) sBn[tid] = bnp[tid];

    unsigned baseAhi = (unsigned)__cvta_generic_to_shared(sAhi);
    unsigned baseAlo = (unsigned)__cvta_generic_to_shared(sAlo);
    unsigned baseBhi = (unsigned)__cvta_generic_to_shared(sBhi);
    unsigned baseBlo = (unsigned)__cvta_generic_to_shared(sBlo);
    int lm = lane >> 3, lr = lane & 7;
    unsigned offA = ((( (lm & 1) * 8 + lr) * SWH)  + (lm >> 1) * 4) * 4;
    unsigned offB = ((( (lm >> 1) * 8 + lr) * SWBS) + (lm & 1) * 4) * 4;

    // per-thread staging indices
    int ar_m = tid >> 2, aq_m = tid & 3;             // mean path: 2 tasks (rows ar_m, ar_m+64)
    int ar_f = tid >> 3, ac_f = tid & 7;             // feat path: 4 tasks (rows +0,32,64,96)
    int bn_i = tid >> 2, bq_i = tid & 3;             // B path: 2 tasks (n, n+64)
    __syncthreads();

    float acc[2][8][4];
    #pragma unroll
    for (int m = 0; m < 2; m++)
        #pragma unroll
        for (int n = 0; n < 8; n++)
            #pragma unroll
            for (int i = 0; i < 4; i++) acc[m][n][i] = 0.0f;

    uint4 pa[4], pb[4];

    // ---- issue loads for a chunk into registers ----
    #define ISSUE(chunk) do {                                                     \
        bool ismean = ((chunk) < 4);                                              \
        int kb2 = ((chunk) & 3) * 16;                                             \
        const unsigned* bh = ismean ? whl : whr;                                  \
        const unsigned* bl = ismean ? wll : wlr;                                  \
        if (ismean) {                                                             \
            _Pragma("unroll")                                                     \
            for (int i = 0; i < 2; i++) {                                         \
                int r = ar_m + i * 64;                                            \
                int row = row0 + r;                                               \
                uint4 vh = make_uint4(0,0,0,0), vl = make_uint4(0,0,0,0);         \
                if (row < nrows) {                                                \
                    size_t g = (size_t)row * WPR + kb2 + 4*aq_m;                  \
                    vh = *reinterpret_cast<const uint4*>(meanh + g);              \
                    vl = *reinterpret_cast<const uint4*>(meanl + g);              \
                }                                                                 \
                pa[2*i] = vh; pa[2*i+1] = vl;                                     \
            }                                                                     \
        } else {                                                                  \
            int kbase = ((chunk) & 3) * 32;                                       \
            _Pragma("unroll")                                                     \
            for (int i = 0; i < 4; i++) {                                         \
                int row = row0 + ar_f + i * 32;                                   \
                uint4 v = make_uint4(0,0,0,0);                                    \
                if (row < nrows)                                                  \
                    v = *reinterpret_cast<const uint4*>(                          \
                        feat + (size_t)row * HIDF + kbase + 4*ac_f);              \
                pa[i] = v;                                                        \
            }                                                                     \
        }                                                                         \
        _Pragma("unroll")                                                         \
        for (int i = 0; i < 2; i++) {                                             \
            int n = bn_i + i * 64;                                                \
            size_t g = (size_t)n * WPR + kb2 + 4*bq_i;                            \
            pb[2*i]   = *reinterpret_cast<const uint4*>(bh + g);                  \
            pb[2*i+1] = *reinterpret_cast<const uint4*>(bl + g);                  \
        }                                                                         \
    } while (0)

    // ---- store registers into smem (with transform on feat path) ----
    #define STORE(chunk) do {                                                     \
        bool ismean = ((chunk) < 4);                                              \
        if (ismean) {                                                             \
            _Pragma("unroll")                                                     \
            for (int i = 0; i < 2; i++) {                                         \
                int r = ar_m + i * 64;                                            \
                *reinterpret_cast<uint4*>(sAhi + r * SWH + 4*aq_m) = pa[2*i];     \
                *reinterpret_cast<uint4*>(sAlo + r * SWH + 4*aq_m) = pa[2*i+1];   \
            }                                                                     \
        } else {                                                                  \
            int kbase = ((chunk) & 3) * 32;                                       \
            _Pragma("unroll")                                                     \
            for (int i = 0; i < 4; i++) {                                         \
                int r = ar_f + i * 32;                                            \
                float4 v = make_float4(__uint_as_float(pa[i].x),                  \
                                       __uint_as_float(pa[i].y),                  \
                                       __uint_as_float(pa[i].z),                  \
                                       __uint_as_float(pa[i].w));                 \
                if (hasbn) {                                                      \
                    int cc = kbase + 4*ac_f;                                      \
                    v.x = fmaxf(fmaf(v.x, sBn[cc+0], sBn[128+cc+0]), 0.f);        \
                    v.y = fmaxf(fmaf(v.y, sBn[cc+1], sBn[128+cc+1]), 0.f);        \
                    v.z = fmaxf(fmaf(v.z, sBn[cc+2], sBn[128+cc+2]), 0.f);        \
                    v.w = fmaxf(fmaf(v.w, sBn[cc+3], sBn[128+cc+3]), 0.f);        \
                }                                                                 \
                unsigned h[2], l[2];                                              \
                split4(v, h, l);                                                  \
                *reinterpret_cast<uint2*>(sAhi + r * SWH + ac_f * 2) =            \
                    make_uint2(h[0], h[1]);                                       \
                *reinterpret_cast<uint2*>(sAlo + r * SWH + ac_f * 2) =            \
                    make_uint2(l[0], l[1]);                                       \
            }                                                                     \
        }                                                                         \
        _Pragma("unroll")                                                         \
        for (int i = 0; i < 2; i++) {                                             \
            int n = bn_i + i * 64;                                                \
            *reinterpret_cast<uint4*>(sBhi + n * SWBS + 4*bq_i) = pb[2*i];        \
            *reinterpret_cast<uint4*>(sBlo + n * SWBS + 4*bq_i) = pb[2*i+1];      \
        }                                                                         \
    } while (0)

    ISSUE(0);
    for (int chunk = 0; chunk < 8; chunk++) {
        STORE(chunk);
        __syncthreads();
        if (chunk < 7) {
            // issue next chunk's loads; consumed only at next STORE -> overlap with mma
            switch (chunk + 1) {
                case 1: ISSUE(1); break;
                case 2: ISSUE(2); break;
                case 3: ISSUE(3); break;
                case 4: ISSUE(4); break;
                case 5: ISSUE(5); break;
                case 6: ISSUE(6); break;
                case 7: ISSUE(7); break;
            }
        }
        #pragma unroll
        for (int s = 0; s < 2; s++) {
            int wb = s * 8;
            unsigned ah[2][4], al[2][4];
            #pragma unroll
            for (int mt = 0; mt < 2; mt++) {
                unsigned ao = (((r0w + mt*16) * SWH) + wb) * 4;
                ldsm_x4(ah[mt], baseAhi + offA + ao);
                ldsm_x4(al[mt], baseAlo + offA + ao);
            }
            #pragma unroll
            for (int p = 0; p < 4; p++) {
                unsigned bhf[4], blf[4];
                unsigned bo = (((n0w + p*16) * SWBS) + wb) * 4;
                ldsm_x4(bhf, baseBhi + offB + bo);
                ldsm_x4(blf, baseBlo + offB + bo);
                #pragma unroll
                for (int mt = 0; mt < 2; mt++) {
                    MMA_BF16(acc[mt][2*p],   ah[mt][0],ah[mt][1],ah[mt][2],ah[mt][3], bhf[0],bhf[1]);
                    MMA_BF16(acc[mt][2*p],   ah[mt][0],ah[mt][1],ah[mt][2],ah[mt][3], blf[0],blf[1]);
                    MMA_BF16(acc[mt][2*p],   al[mt][0],al[mt][1],al[mt][2],al[mt][3], bhf[0],bhf[1]);
                    MMA_BF16(acc[mt][2*p+1], ah[mt][0],ah[mt][1],ah[mt][2],ah[mt][3], bhf[2],bhf[3]);
                    MMA_BF16(acc[mt][2*p+1], ah[mt][0],ah[mt][1],ah[mt][2],ah[mt][3], blf[2],blf[3]);
                    MMA_BF16(acc[mt][2*p+1], al[mt][0],al[mt][1],al[mt][2],al[mt][3], bhf[2],bhf[3]);
                }
            }
        }
        __syncthreads();
    }
    #undef ISSUE
    #undef STORE

    // write out
    #pragma unroll
    for (int mt = 0; mt < 2; mt++) {
        int rowa = row0 + r0w + mt*16 + qr;
        int rowb = rowa + 8;
        #pragma unroll
        for (int nt = 0; nt < 8; nt++) {
            int col = n0w + nt*8 + 2*qc;
            if (rowa < nrows)
                *reinterpret_cast<float2*>(out + (size_t)rowa * HIDF + col) =
                    make_float2(acc[mt][nt][0], acc[mt][nt][1]);
            if (rowb < nrows)
                *reinterpret_cast<float2*>(out + (size_t)rowb * HIDF + col) =
                    make_float2(acc[mt][nt][2], acc[mt][nt][3]);
        }
    }

    // fused BN statistics
    #pragma unroll
    for (int nt = 0; nt < 8; nt++) {
        #pragma unroll
        for (int p = 0; p < 2; p++) {
            float v0 = acc[0][nt][p],   v1 = acc[0][nt][p+2];
            float v2 = acc[1][nt][p],   v3 = acc[1][nt][p+2];
            float s = v0 + v1 + v2 + v3;
            float q = v0*v0 + v1*v1 + v2*v2 + v3*v3;
            #pragma unroll
            for (int off = 4; off < 32; off <<= 1) {
                s += __shfl_xor_sync(0xffffffff, s, off);
                q += __shfl_xor_sync(0xffffffff, q, off);
            }
            if (qr == 0) {
                int col = n0w + nt*8 + 2*qc + p;
                redg_f32(stats + col, s);
                redg_f32(stats + 128 + col, q);
            }
        }
    }
}

// ---- bn finalize ----
__global__ void bn_finalize_kernel(const float* __restrict__ stats,
                                   const float* __restrict__ g,
                                   const float* __restrict__ be,
                                   float* __restrict__ bnp, int nrows) {
    int c = threadIdx.x;
    float invN = 1.0f / (float)nrows;
    float mu  = stats[c] * invN;
    float var = stats[128 + c] * invN - mu * mu;
    float sc  = g[c] * rsqrtf(var + BN_EPS);
    bnp[c]       = sc;
    bnp[128 + c] = be[c] - mu * sc;
}

// ---- NC=40 variant (unchanged pipeline shape; small kernel) ----
__global__ void __launch_bounds__(256)
gemm_tc40_kernel(const unsigned* __restrict__ meanh,
                 const unsigned* __restrict__ meanl,
                 const float* __restrict__ feat,
                 const float* __restrict__ bnp,
                 const unsigned* __restrict__ whl, const unsigned* __restrict__ wll,
                 const unsigned* __restrict__ whr, const unsigned* __restrict__ wlr,
                 const float* __restrict__ bias,
                 float* __restrict__ out, int nrows) {
    __shared__ unsigned sAhi[128 * SWH];
    __shared__ unsigned sAlo[128 * SWH];
    __shared__ unsigned sBhi[48 * SWBS];
    __shared__ unsigned sBlo[48 * SWBS];
    __shared__ float    sBn[256];

    int tid  = threadIdx.x;
    int row0 = blockIdx.x * 128;
    int lane = tid & 31;
    int wid  = tid >> 5;
    int qr = lane >> 2, qc = lane & 3;
    int r0w = wid * 16;

    if (tid < 256) sBn[tid] = bnp[tid];

    unsigned baseAhi = (unsigned)__cvta_generic_to_shared(sAhi);
    unsigned baseAlo = (unsigned)__cvta_generic_to_shared(sAlo);
    unsigned baseBhi = (unsigned)__cvta_generic_to_shared(sBhi);
    unsigned baseBlo = (unsigned)__cvta_generic_to_shared(sBlo);
    int lm = lane >> 3, lr = lane & 7;
    unsigned offA = ((( (lm & 1) * 8 + lr) * SWH)  + (lm >> 1) * 4) * 4;
    unsigned offB = ((( (lm >> 1) * 8 + lr) * SWBS) + (lm & 1) * 4) * 4;
    __syncthreads();

    float acc[6][4];
    #pragma unroll
    for (int n = 0; n < 6; n++)
        #pragma unroll
        for (int i = 0; i < 4; i++) acc[n][i] = 0.0f;

    for (int chunk = 0; chunk < 8; chunk++) {
        bool ismean = (chunk < 4);
        int kb2 = (chunk & 3) * 16;
        const unsigned* bh = ismean ? whl : whr;
        const unsigned* bl = ismean ? wll : wlr;

        if (ismean) {
            #pragma unroll
            for (int i = 0; i < 2; i++) {
                int t = i * 256 + tid;
                int r = t >> 2;
                int q = t & 3;
                int row = row0 + r;
                uint4 vh = make_uint4(0,0,0,0), vl = make_uint4(0,0,0,0);
                if (row < nrows) {
                    size_t g = (size_t)row * WPR + kb2 + 4*q;
                    vh = *reinterpret_cast<const uint4*>(meanh + g);
                    vl = *reinterpret_cast<const uint4*>(meanl + g);
                }
                *reinterpret_cast<uint4*>(sAhi + r * SWH + 4*q) = vh;
                *reinterpret_cast<uint4*>(sAlo + r * SWH + 4*q) = vl;
            }
        } else {
            int kbase = (chunk & 3) * 32;
            #pragma unroll
            for (int i = 0; i < 4; i++) {
                int t = i * 256 + tid;
                int r  = t >> 3;
                int c4 = t & 7;
                int row = row0 + r;
                float4 v = make_float4(0.f,0.f,0.f,0.f);
                if (row < nrows) {
                    v = *reinterpret_cast<const float4*>(feat + (size_t)row * HIDF + kbase + 4*c4);
                    int cc = kbase + 4*c4;
                    v.x = fmaxf(fmaf(v.x, sBn[cc+0], sBn[128+cc+0]), 0.f);
                    v.y = fmaxf(fmaf(v.y, sBn[cc+1], sBn[128+cc+1]), 0.f);
                    v.z = fmaxf(fmaf(v.z, sBn[cc+2], sBn[128+cc+2]), 0.f);
                    v.w = fmaxf(fmaf(v.w, sBn[cc+3], sBn[128+cc+3]), 0.f);
                }
                unsigned h[2], l[2];
                split4(v, h, l);
                *reinterpret_cast<uint2*>(sAhi + r * SWH + c4 * 2) = make_uint2(h[0], h[1]);
                *reinterpret_cast<uint2*>(sAlo + r * SWH + c4 * 2) = make_uint2(l[0], l[1]);
            }
        }
        if (tid < 160) {
            int n = tid >> 2;
            int q = tid & 3;
            size_t g = (size_t)n * WPR + kb2 + 4*q;
            *reinterpret_cast<uint4*>(sBhi + n * SWBS + 4*q) =
                *reinterpret_cast<const uint4*>(bh + g);
            *reinterpret_cast<uint4*>(sBlo + n * SWBS + 4*q) =
                *reinterpret_cast<const uint4*>(bl + g);
        }
        __syncthreads();

        #pragma unroll
        for (int s = 0; s < 2; s++) {
            int wb = s * 8;
            unsigned ah[4], al[4];
            unsigned ao = ((r0w * SWH) + wb) * 4;
            ldsm_x4(ah, baseAhi + offA + ao);
            ldsm_x4(al, baseAlo + offA + ao);
            #pragma unroll
            for (int p = 0; p < 3; p++) {
                unsigned bhf[4], blf[4];
                unsigned bo = (((p*16) * SWBS) + wb) * 4;
                ldsm_x4(bhf, baseBhi + offB + bo);
                ldsm_x4(blf, baseBlo + offB + bo);
                MMA_BF16(acc[2*p],   ah[0],ah[1],ah[2],ah[3], bhf[0],bhf[1]);
                MMA_BF16(acc[2*p],   ah[0],ah[1],ah[2],ah[3], blf[0],blf[1]);
                MMA_BF16(acc[2*p],   al[0],al[1],al[2],al[3], bhf[0],bhf[1]);
                MMA_BF16(acc[2*p+1], ah[0],ah[1],ah[2],ah[3], bhf[2],bhf[3]);
                MMA_BF16(acc[2*p+1], ah[0],ah[1],ah[2],ah[3], blf[2],blf[3]);
                MMA_BF16(acc[2*p+1], al[0],al[1],al[2],al[3], bhf[2],bhf[3]);
            }
        }
        __syncthreads();
    }

    int rowa = row0 + r0w + qr;
    int rowb = rowa + 8;
    #pragma unroll
    for (int nt = 0; nt < 5; nt++) {
        int col = nt*8 + 2*qc;
        float b0 = bias[col], b1 = bias[col+1];
        if (rowa < nrows)
            *reinterpret_cast<float2*>(out + (size_t)rowa * OUTF + col) =
                make_float2(acc[nt][0] + b0, acc[nt][1] + b1);
        if (rowb < nrows)
            *reinterpret_cast<float2*>(out + (size_t)rowb * OUTF + col) =
                make_float2(acc[nt][2] + b0, acc[nt][3] + b1);
    }
}

// ---------------- launch ----------------
extern "C" void kernel_launch(void* const* d_in, const int* in_sizes, int n_in,
                              void* d_out, int out_size) {
    const float* x   = (const float*)d_in[0];
    const int*   ei  = (const int*)d_in[1];
    const float* Wl0 = (const float*)d_in[2];
    const float* Wr0 = (const float*)d_in[3];
    const float* Wl1 = (const float*)d_in[4];
    const float* Wr1 = (const float*)d_in[5];
    const float* Wl2 = (const float*)d_in[6];
    const float* Wr2 = (const float*)d_in[7];
    const float* b2  = (const float*)d_in[8];
    const float* g0  = (const float*)d_in[9];
    const float* be0 = (const float*)d_in[10];
    const float* g1  = (const float*)d_in[11];
    const float* be1 = (const float*)d_in[12];
    float* out = (float*)d_out;

    int E = in_sizes[1] / 2;
    int N = in_sizes[0] / HIDF;

    float *h0, *h1, *sums, *bnp0, *bnp1;
    unsigned *meanh, *meanl, *wh, *wl;
    int *rowptr, *cursor, *csr, *bsum;
    cudaGetSymbolAddress((void**)&meanh, g_meanh);
    cudaGetSymbolAddress((void**)&meanl, g_meanl);
    cudaGetSymbolAddress((void**)&h0,    g_h0);
    cudaGetSymbolAddress((void**)&h1,    g_h1);
    cudaGetSymbolAddress((void**)&sums,  g_sums);
    cudaGetSymbolAddress((void**)&bnp0,  g_bnp0);
    cudaGetSymbolAddress((void**)&bnp1,  g_bnp1);
    cudaGetSymbolAddress((void**)&rowptr, g_rowptr);
    cudaGetSymbolAddress((void**)&cursor, g_cursor);
    cudaGetSymbolAddress((void**)&csr,    g_csr);
    cudaGetSymbolAddress((void**)&bsum,   g_bsum);
    cudaGetSymbolAddress((void**)&wh,     g_wh);
    cudaGetSymbolAddress((void**)&wl,     g_wl);

    int np1 = N + 1;
    int nscan = (np1 + 1023) / 1024;
    int tc_blocks = (N + 127) / 128;
    int ga_blocks = (N + 7) / 8;

    // ---- CSR build + weight pre-split ----
    zero_int_kernel<<<(np1 + 255) / 256, 256>>>(rowptr, np1);
    degree_kernel<<<(E + 255) / 256, 256>>>(ei, rowptr, E, N);
    scan1_kernel<<<nscan, 1024>>>(rowptr, bsum, np1);
    scan2_kernel<<<1, 1024>>>(bsum, nscan);
    scan3_kernel<<<nscan, 1024>>>(rowptr, bsum, cursor, np1, N);
    fill_kernel<<<(E + 255) / 256, 256>>>(ei, cursor, csr, E, N);
    zero_f_kernel<<<1, 512>>>(sums, 512);
    splitw_kernel<<<(WTOT + 255) / 256, 256>>>(Wl0, Wr0, Wl1, Wr1, Wl2, Wr2, wh, wl);

    // ---- layer 0 ----
    gather_kernel<<<ga_blocks, 256>>>(x, rowptr, csr, nullptr, meanh, meanl, N);
    gemm_tc128_kernel<<<tc_blocks, 256>>>(meanh, meanl, x, nullptr,
                                          wh + WOFF_L0, wl + WOFF_L0,
                                          wh + WOFF_R0, wl + WOFF_R0,
                                          h0, sums, N);
    bn_finalize_kernel<<<1, 128>>>(sums, g0, be0, bnp0, N);

    // ---- layer 1 ----
    gather_kernel<<<ga_blocks, 256>>>(h0, rowptr, csr, bnp0, meanh, meanl, N);
    gemm_tc128_kernel<<<tc_blocks, 256>>>(meanh, meanl, h0, bnp0,
                                          wh + WOFF_L1, wl + WOFF_L1,
                                          wh + WOFF_R1, wl + WOFF_R1,
                                          h1, sums + 256, N);
    bn_finalize_kernel<<<1, 128>>>(sums + 256, g1, be1, bnp1, N);

    // ---- layer 2 ----
    gather_kernel<<<ga_blocks, 256>>>(h1, rowptr, csr, bnp1, meanh, meanl, N);
    gemm_tc40_kernel<<<tc_blocks, 256>>>(meanh, meanl, h1, bnp1,
                                         wh + WOFF_L2, wl + WOFF_L2,
                                         wh + WOFF_R2, wl + WOFF_R2,
                                         b2, out, N);
}

// round 16
// speedup vs baseline: 1.0022x; 1.0022x over previous
#include <cuda_runtime.h>
#include <cuda_bf16.h>
#include <cstdint>

#define N_NODES 100000
#define E_EDGES 800000
#define HIDF 128
#define OUTF 40
#define BN_EPS 1e-5f
#define WPR 64          // bf16x2 words per feature row (128 bf16)

// ---------------- scratch ----------------
__device__ unsigned g_meanh[(size_t)N_NODES * WPR];
__device__ unsigned g_meanl[(size_t)N_NODES * WPR];
__device__ float g_h0 [(size_t)N_NODES * HIDF];
__device__ float g_h1 [(size_t)N_NODES * HIDF];
__device__ int   g_rowptr[N_NODES + 1];
__device__ int   g_cursor[N_NODES];
__device__ int   g_csr[E_EDGES];
__device__ int   g_bsum[1024];
__device__ float g_sums[512];
__device__ float g_bnp0[256];
__device__ float g_bnp1[256];
#define WOFF_L0 0
#define WOFF_R0 8192
#define WOFF_L1 16384
#define WOFF_R1 24576
#define WOFF_L2 32768
#define WOFF_R2 35328
#define WTOT    37888
__device__ unsigned g_wh[WTOT];
__device__ unsigned g_wl[WTOT];

// ---------------- helpers ----------------
__device__ __forceinline__ unsigned pack_bf16x2(float lo, float hi) {
    unsigned r;
    asm("cvt.rn.bf16x2.f32 %0, %1, %2;" : "=r"(r) : "f"(hi), "f"(lo));
    return r;
}
__device__ __forceinline__ float bf_lo(unsigned u) { return __uint_as_float(u << 16); }
__device__ __forceinline__ float bf_hi(unsigned u) { return __uint_as_float(u & 0xffff0000u); }

__device__ __forceinline__ void split4(float4 v, unsigned* h, unsigned* l) {
    h[0] = pack_bf16x2(v.x, v.y);
    h[1] = pack_bf16x2(v.z, v.w);
    l[0] = pack_bf16x2(v.x - bf_lo(h[0]), v.y - bf_hi(h[0]));
    l[1] = pack_bf16x2(v.z - bf_lo(h[1]), v.w - bf_hi(h[1]));
}

#define MMA_BF16(d, A0,A1,A2,A3, B0,B1) \
    asm volatile("mma.sync.aligned.m16n8k16.row.col.f32.bf16.bf16.f32 " \
        "{%0,%1,%2,%3}, {%4,%5,%6,%7}, {%8,%9}, {%0,%1,%2,%3};" \
        : "+f"((d)[0]), "+f"((d)[1]), "+f"((d)[2]), "+f"((d)[3]) \
        : "r"(A0), "r"(A1), "r"(A2), "r"(A3), "r"(B0), "r"(B1))

__device__ __forceinline__ void ldsm_x4(unsigned* r, unsigned addr) {
    asm volatile("ldmatrix.sync.aligned.m8n8.x4.shared.b16 {%0,%1,%2,%3}, [%4];"
                 : "=r"(r[0]), "=r"(r[1]), "=r"(r[2]), "=r"(r[3]) : "r"(addr));
}

__device__ __forceinline__ void redg_f32(float* p, float v) {
    asm volatile("red.global.add.f32 [%0], %1;" :: "l"(p), "f"(v) : "memory");
}

// ---------------- small utils ----------------
__global__ void zero_int_kernel(int* __restrict__ p, int n) {
    int i = blockIdx.x * blockDim.x + threadIdx.x;
    if (i < n) p[i] = 0;
}
__global__ void zero_f_kernel(float* __restrict__ p, int n) {
    int i = blockIdx.x * blockDim.x + threadIdx.x;
    if (i < n) p[i] = 0.0f;
}

// ---------------- weight pre-split ----------------
__global__ void splitw_kernel(const float* __restrict__ Wl0, const float* __restrict__ Wr0,
                              const float* __restrict__ Wl1, const float* __restrict__ Wr1,
                              const float* __restrict__ Wl2, const float* __restrict__ Wr2,
                              unsigned* __restrict__ wh, unsigned* __restrict__ wl) {
    int i = blockIdx.x * blockDim.x + threadIdx.x;
    if (i >= WTOT) return;
    const float* src; int idx, NC;
    if      (i < WOFF_R0) { src = Wl0; idx = i;            NC = 128; }
    else if (i < WOFF_L1) { src = Wr0; idx = i - WOFF_R0;  NC = 128; }
    else if (i < WOFF_R1) { src = Wl1; idx = i - WOFF_L1;  NC = 128; }
    else if (i < WOFF_L2) { src = Wr1; idx = i - WOFF_R1;  NC = 128; }
    else if (i < WOFF_R2) { src = Wl2; idx = i - WOFF_L2;  NC = OUTF; }
    else                  { src = Wr2; idx = i - WOFF_R2;  NC = OUTF; }
    int n = idx >> 6, kw = idx & 63;
    float v0 = src[(size_t)(2*kw)     * NC + n];
    float v1 = src[(size_t)(2*kw + 1) * NC + n];
    unsigned h = pack_bf16x2(v0, v1);
    unsigned l = pack_bf16x2(v0 - bf_lo(h), v1 - bf_hi(h));
    wh[i] = h; wl[i] = l;
}

// ---------------- CSR build ----------------
__global__ void degree_kernel(const int* __restrict__ ei, int* __restrict__ rowptr,
                              int E, int N) {
    int e = blockIdx.x * blockDim.x + threadIdx.x;
    if (e >= E) return;
    int s = ei[e], d = ei[E + e];
    if ((unsigned)s < (unsigned)N && (unsigned)d < (unsigned)N)
        atomicAdd(&rowptr[d + 1], 1);
}

__global__ void scan1_kernel(int* __restrict__ data, int* __restrict__ bsum, int n) {
    __shared__ int sh[1024];
    int gid = blockIdx.x * 1024 + threadIdx.x;
    int v = (gid < n) ? data[gid] : 0;
    sh[threadIdx.x] = v;
    __syncthreads();
    #pragma unroll
    for (int off = 1; off < 1024; off <<= 1) {
        int t = (threadIdx.x >= off) ? sh[threadIdx.x - off] : 0;
        __syncthreads();
        sh[threadIdx.x] += t;
        __syncthreads();
    }
    if (gid < n) data[gid] = sh[threadIdx.x];
    if (threadIdx.x == 1023) bsum[blockIdx.x] = sh[1023];
}

__global__ void scan2_kernel(int* __restrict__ bsum, int nb) {
    __shared__ int sh[1024];
    int v = (threadIdx.x < nb) ? bsum[threadIdx.x] : 0;
    sh[threadIdx.x] = v;
    __syncthreads();
    #pragma unroll
    for (int off = 1; off < 1024; off <<= 1) {
        int t = (threadIdx.x >= off) ? sh[threadIdx.x - off] : 0;
        __syncthreads();
        sh[threadIdx.x] += t;
        __syncthreads();
    }
    if (threadIdx.x < nb) bsum[threadIdx.x] = sh[threadIdx.x];
}

__global__ void scan3_kernel(int* __restrict__ data, const int* __restrict__ bsum,
                             int* __restrict__ cursor, int n, int N) {
    int gid = blockIdx.x * 1024 + threadIdx.x;
    if (gid >= n) return;
    int add = (blockIdx.x > 0) ? bsum[blockIdx.x - 1] : 0;
    int v = data[gid] + add;
    data[gid] = v;
    if (gid < N) cursor[gid] = v;
}

__global__ void fill_kernel(const int* __restrict__ ei, int* __restrict__ cursor,
                            int* __restrict__ csr, int E, int N) {
    int e = blockIdx.x * blockDim.x + threadIdx.x;
    if (e >= E) return;
    int s = ei[e], d = ei[E + e];
    if ((unsigned)s >= (unsigned)N || (unsigned)d >= (unsigned)N) return;
    int pos = atomicAdd(&cursor[d], 1);
    csr[pos] = s;
}

// ---------------- gather-mean, writes split bf16 hi/lo words ----------------
__global__ void __launch_bounds__(256)
gather_kernel(const float* __restrict__ feat,
              const int* __restrict__ rowptr,
              const int* __restrict__ csr,
              const float* __restrict__ bnp,
              unsigned* __restrict__ meanh,
              unsigned* __restrict__ meanl, int N) {
    int node = blockIdx.x * 8 + (threadIdx.x >> 5);
    if (node >= N) return;
    int c = (threadIdx.x & 31) << 2;

    float4 sc = make_float4(1.f,1.f,1.f,1.f), sh = make_float4(0.f,0.f,0.f,0.f);
    bool bn = (bnp != nullptr);
    if (bn) {
        sc = *reinterpret_cast<const float4*>(bnp + c);
        sh = *reinterpret_cast<const float4*>(bnp + 128 + c);
    }

    int beg = rowptr[node], end = rowptr[node + 1];
    float4 acc = make_float4(0.f,0.f,0.f,0.f);
    int j = beg;
    for (; j + 4 <= end; j += 4) {
        int i0 = csr[j], i1 = csr[j+1], i2 = csr[j+2], i3 = csr[j+3];
        float4 v0 = *reinterpret_cast<const float4*>(feat + (size_t)i0 * HIDF + c);
        float4 v1 = *reinterpret_cast<const float4*>(feat + (size_t)i1 * HIDF + c);
        float4 v2 = *reinterpret_cast<const float4*>(feat + (size_t)i2 * HIDF + c);
        float4 v3 = *reinterpret_cast<const float4*>(feat + (size_t)i3 * HIDF + c);
        if (bn) {
            v0.x=fmaxf(fmaf(v0.x,sc.x,sh.x),0.f); v0.y=fmaxf(fmaf(v0.y,sc.y,sh.y),0.f);
            v0.z=fmaxf(fmaf(v0.z,sc.z,sh.z),0.f); v0.w=fmaxf(fmaf(v0.w,sc.w,sh.w),0.f);
            v1.x=fmaxf(fmaf(v1.x,sc.x,sh.x),0.f); v1.y=fmaxf(fmaf(v1.y,sc.y,sh.y),0.f);
            v1.z=fmaxf(fmaf(v1.z,sc.z,sh.z),0.f); v1.w=fmaxf(fmaf(v1.w,sc.w,sh.w),0.f);
            v2.x=fmaxf(fmaf(v2.x,sc.x,sh.x),0.f); v2.y=fmaxf(fmaf(v2.y,sc.y,sh.y),0.f);
            v2.z=fmaxf(fmaf(v2.z,sc.z,sh.z),0.f); v2.w=fmaxf(fmaf(v2.w,sc.w,sh.w),0.f);
            v3.x=fmaxf(fmaf(v3.x,sc.x,sh.x),0.f); v3.y=fmaxf(fmaf(v3.y,sc.y,sh.y),0.f);
            v3.z=fmaxf(fmaf(v3.z,sc.z,sh.z),0.f); v3.w=fmaxf(fmaf(v3.w,sc.w,sh.w),0.f);
        }
        acc.x += v0.x + v1.x + v2.x + v3.x;
        acc.y += v0.y + v1.y + v2.y + v3.y;
        acc.z += v0.z + v1.z + v2.z + v3.z;
        acc.w += v0.w + v1.w + v2.w + v3.w;
    }
    for (; j < end; j++) {
        int i0 = csr[j];
        float4 v0 = *reinterpret_cast<const float4*>(feat + (size_t)i0 * HIDF + c);
        if (bn) {
            v0.x=fmaxf(fmaf(v0.x,sc.x,sh.x),0.f); v0.y=fmaxf(fmaf(v0.y,sc.y,sh.y),0.f);
            v0.z=fmaxf(fmaf(v0.z,sc.z,sh.z),0.f); v0.w=fmaxf(fmaf(v0.w,sc.w,sh.w),0.f);
        }
        acc.x += v0.x; acc.y += v0.y; acc.z += v0.z; acc.w += v0.w;
    }
    float invd = (end > beg) ? 1.0f / (float)(end - beg) : 0.0f;
    acc.x *= invd; acc.y *= invd; acc.z *= invd; acc.w *= invd;
    unsigned h[2], l[2];
    split4(acc, h, l);
    size_t w = (size_t)node * WPR + (c >> 1);
    *reinterpret_cast<uint2*>(meanh + w) = make_uint2(h[0], h[1]);
    *reinterpret_cast<uint2*>(meanl + w) = make_uint2(l[0], l[1]);
}

// ======== bf16 3x-split TC GEMM, ldmatrix fragments, register-prefetch pipeline =====
#define SWH  20
#define SWBS 20

__global__ void __launch_bounds__(256, 2)
gemm_tc128_kernel(const unsigned* __restrict__ meanh,
                  const unsigned* __restrict__ meanl,
                  const float* __restrict__ feat,
                  const float* __restrict__ bnp,
                  const unsigned* __restrict__ whl, const unsigned* __restrict__ wll,
                  const unsigned* __restrict__ whr, const unsigned* __restrict__ wlr,
                  float* __restrict__ out,
                  float* __restrict__ stats,
                  int nrows) {
    __shared__ unsigned sAhi[128 * SWH];
    __shared__ unsigned sAlo[128 * SWH];
    __shared__ unsigned sBhi[128 * SWBS];
    __shared__ unsigned sBlo[128 * SWBS];
    __shared__ float    sBn[256];

    int tid  = threadIdx.x;
    int row0 = blockIdx.x * 128;
    int lane = tid & 31;
    int wid  = tid >> 5;
    int qr = lane >> 2, qc = lane & 3;
    int r0w = (wid & 3) * 32;
    int n0w = (wid >> 2) * 64;
    bool hasbn = (bnp != nullptr);

    if (hasbn && tid < 256) sBn[tid] = bnp[tid];

    unsigned baseAhi = (unsigned)__cvta_generic_to_shared(sAhi);
    unsigned baseAlo = (unsigned)__cvta_generic_to_shared(sAlo);
    unsigned baseBhi = (unsigned)__cvta_generic_to_shared(sBhi);
    unsigned baseBlo = (unsigned)__cvta_generic_to_shared(sBlo);
    int lm = lane >> 3, lr = lane & 7;
    unsigned offA = ((( (lm & 1) * 8 + lr) * SWH)  + (lm >> 1) * 4) * 4;
    unsigned offB = ((( (lm >> 1) * 8 + lr) * SWBS) + (lm & 1) * 4) * 4;

    // per-thread staging indices
    int ar_m = tid >> 2, aq_m = tid & 3;             // mean path: 2 tasks (rows ar_m, ar_m+64)
    int ar_f = tid >> 3, ac_f = tid & 7;             // feat path: 4 tasks (rows +0,32,64,96)
    int bn_i = tid >> 2, bq_i = tid & 3;             // B path: 2 tasks (n, n+64)
    __syncthreads();

    float acc[2][8][4];
    #pragma unroll
    for (int m = 0; m < 2; m++)
        #pragma unroll
        for (int n = 0; n < 8; n++)
            #pragma unroll
            for (int i = 0; i < 4; i++) acc[m][n][i] = 0.0f;

    uint4 pa[4], pb[4];

    // ---- issue loads for a chunk into registers ----
    #define ISSUE(chunk) do {                                                     \
        bool ismean = ((chunk) < 4);                                              \
        int kb2 = ((chunk) & 3) * 16;                                             \
        const unsigned* bh = ismean ? whl : whr;                                  \
        const unsigned* bl = ismean ? wll : wlr;                                  \
        if (ismean) {                                                             \
            _Pragma("unroll")                                                     \
            for (int i = 0; i < 2; i++) {                                         \
                int r = ar_m + i * 64;                                            \
                int row = row0 + r;                                               \
                uint4 vh = make_uint4(0,0,0,0), vl = make_uint4(0,0,0,0);         \
                if (row < nrows) {                                                \
                    size_t g = (size_t)row * WPR + kb2 + 4*aq_m;                  \
                    vh = *reinterpret_cast<const uint4*>(meanh + g);              \
                    vl = *reinterpret_cast<const uint4*>(meanl + g);              \
                }                                                                 \
                pa[2*i] = vh; pa[2*i+1] = vl;                                     \
            }                                                                     \
        } else {                                                                  \
            int kbase = ((chunk) & 3) * 32;                                       \
            _Pragma("unroll")                                                     \
            for (int i = 0; i < 4; i++) {                                         \
                int row = row0 + ar_f + i * 32;                                   \
                uint4 v = make_uint4(0,0,0,0);                                    \
                if (row < nrows)                                                  \
                    v = *reinterpret_cast<const uint4*>(                          \
                        feat + (size_t)row * HIDF + kbase + 4*ac_f);              \
                pa[i] = v;                                                        \
            }                                                                     \
        }                                                                         \
        _Pragma("unroll")                                                         \
        for (int i = 0; i < 2; i++) {                                             \
            int n = bn_i + i * 64;                                                \
            size_t g = (size_t)n * WPR + kb2 + 4*bq_i;                            \
            pb[2*i]   = *reinterpret_cast<const uint4*>(bh + g);                  \
            pb[2*i+1] = *reinterpret_cast<const uint4*>(bl + g);                  \
        }                                                                         \
    } while (0)

    // ---- store registers into smem (with transform on feat path) ----
    #define STORE(chunk) do {                                                     \
        bool ismean = ((chunk) < 4);                                              \
        if (ismean) {                                                             \
            _Pragma("unroll")                                                     \
            for (int i = 0; i < 2; i++) {                                         \
                int r = ar_m + i * 64;                                            \
                *reinterpret_cast<uint4*>(sAhi + r * SWH + 4*aq_m) = pa[2*i];     \
                *reinterpret_cast<uint4*>(sAlo + r * SWH + 4*aq_m) = pa[2*i+1];   \
            }                                                                     \
        } else {                                                                  \
            int kbase = ((chunk) & 3) * 32;                                       \
            _Pragma("unroll")                                                     \
            for (int i = 0; i < 4; i++) {                                         \
                int r = ar_f + i * 32;                                            \
                float4 v = make_float4(__uint_as_float(pa[i].x),                  \
                                       __uint_as_float(pa[i].y),                  \
                                       __uint_as_float(pa[i].z),                  \
                                       __uint_as_float(pa[i].w));                 \
                if (hasbn) {                                                      \
                    int cc = kbase + 4*ac_f;                                      \
                    v.x = fmaxf(fmaf(v.x, sBn[cc+0], sBn[128+cc+0]), 0.f);        \
                    v.y = fmaxf(fmaf(v.y, sBn[cc+1], sBn[128+cc+1]), 0.f);        \
                    v.z = fmaxf(fmaf(v.z, sBn[cc+2], sBn[128+cc+2]), 0.f);        \
                    v.w = fmaxf(fmaf(v.w, sBn[cc+3], sBn[128+cc+3]), 0.f);        \
                }                                                                 \
                unsigned h[2], l[2];                                              \
                split4(v, h, l);                                                  \
                *reinterpret_cast<uint2*>(sAhi + r * SWH + ac_f * 2) =            \
                    make_uint2(h[0], h[1]);                                       \
                *reinterpret_cast<uint2*>(sAlo + r * SWH + ac_f * 2) =            \
                    make_uint2(l[0], l[1]);                                       \
            }                                                                     \
        }                                                                         \
        _Pragma("unroll")                                                         \
        for (int i = 0; i < 2; i++) {                                             \
            int n = bn_i + i * 64;                                                \
            *reinterpret_cast<uint4*>(sBhi + n * SWBS + 4*bq_i) = pb[2*i];        \
            *reinterpret_cast<uint4*>(sBlo + n * SWBS + 4*bq_i) = pb[2*i+1];      \
        }                                                                         \
    } while (0)

    ISSUE(0);
    for (int chunk = 0; chunk < 8; chunk++) {
        STORE(chunk);
        __syncthreads();
        if (chunk < 7) {
            // issue next chunk's loads; consumed only at next STORE -> overlap with mma
            switch (chunk + 1) {
                case 1: ISSUE(1); break;
                case 2: ISSUE(2); break;
                case 3: ISSUE(3); break;
                case 4: ISSUE(4); break;
                case 5: ISSUE(5); break;
                case 6: ISSUE(6); break;
                case 7: ISSUE(7); break;
            }
        }
        #pragma unroll
        for (int s = 0; s < 2; s++) {
            int wb = s * 8;
            unsigned ah[2][4], al[2][4];
            #pragma unroll
            for (int mt = 0; mt < 2; mt++) {
                unsigned ao = (((r0w + mt*16) * SWH) + wb) * 4;
                ldsm_x4(ah[mt], baseAhi + offA + ao);
                ldsm_x4(al[mt], baseAlo + offA + ao);
            }
            #pragma unroll
            for (int p = 0; p < 4; p++) {
                unsigned bhf[4], blf[4];
                unsigned bo = (((n0w + p*16) * SWBS) + wb) * 4;
                ldsm_x4(bhf, baseBhi + offB + bo);
                ldsm_x4(blf, baseBlo + offB + bo);
                #pragma unroll
                for (int mt = 0; mt < 2; mt++) {
                    MMA_BF16(acc[mt][2*p],   ah[mt][0],ah[mt][1],ah[mt][2],ah[mt][3], bhf[0],bhf[1]);
                    MMA_BF16(acc[mt][2*p],   ah[mt][0],ah[mt][1],ah[mt][2],ah[mt][3], blf[0],blf[1]);
                    MMA_BF16(acc[mt][2*p],   al[mt][0],al[mt][1],al[mt][2],al[mt][3], bhf[0],bhf[1]);
                    MMA_BF16(acc[mt][2*p+1], ah[mt][0],ah[mt][1],ah[mt][2],ah[mt][3], bhf[2],bhf[3]);
                    MMA_BF16(acc[mt][2*p+1], ah[mt][0],ah[mt][1],ah[mt][2],ah[mt][3], blf[2],blf[3]);
                    MMA_BF16(acc[mt][2*p+1], al[mt][0],al[mt][1],al[mt][2],al[mt][3], bhf[2],bhf[3]);
                }
            }
        }
        __syncthreads();
    }
    #undef ISSUE
    #undef STORE

    // write out
    #pragma unroll
    for (int mt = 0; mt < 2; mt++) {
        int rowa = row0 + r0w + mt*16 + qr;
        int rowb = rowa + 8;
        #pragma unroll
        for (int nt = 0; nt < 8; nt++) {
            int col = n0w + nt*8 + 2*qc;
            if (rowa < nrows)
                *reinterpret_cast<float2*>(out + (size_t)rowa * HIDF + col) =
                    make_float2(acc[mt][nt][0], acc[mt][nt][1]);
            if (rowb < nrows)
                *reinterpret_cast<float2*>(out + (size_t)rowb * HIDF + col) =
                    make_float2(acc[mt][nt][2], acc[mt][nt][3]);
        }
    }

    // fused BN statistics
    #pragma unroll
    for (int nt = 0; nt < 8; nt++) {
        #pragma unroll
        for (int p = 0; p < 2; p++) {
            float v0 = acc[0][nt][p],   v1 = acc[0][nt][p+2];
            float v2 = acc[1][nt][p],   v3 = acc[1][nt][p+2];
            float s = v0 + v1 + v2 + v3;
            float q = v0*v0 + v1*v1 + v2*v2 + v3*v3;
            #pragma unroll
            for (int off = 4; off < 32; off <<= 1) {
                s += __shfl_xor_sync(0xffffffff, s, off);
                q += __shfl_xor_sync(0xffffffff, q, off);
            }
            if (qr == 0) {
                int col = n0w + nt*8 + 2*qc + p;
                redg_f32(stats + col, s);
                redg_f32(stats + 128 + col, q);
            }
        }
    }
}

// ---- bn finalize ----
__global__ void bn_finalize_kernel(const float* __restrict__ stats,
                                   const float* __restrict__ g,
                                   const float* __restrict__ be,
                                   float* __restrict__ bnp, int nrows) {
    int c = threadIdx.x;
    float invN = 1.0f / (float)nrows;
    float mu  = stats[c] * invN;
    float var = stats[128 + c] * invN - mu * mu;
    float sc  = g[c] * rsqrtf(var + BN_EPS);
    bnp[c]       = sc;
    bnp[128 + c] = be[c] - mu * sc;
}

// ---- NC=40 variant (unchanged pipeline shape; small kernel) ----
__global__ void __launch_bounds__(256)
gemm_tc40_kernel(const unsigned* __restrict__ meanh,
                 const unsigned* __restrict__ meanl,
                 const float* __restrict__ feat,
                 const float* __restrict__ bnp,
                 const unsigned* __restrict__ whl, const unsigned* __restrict__ wll,
                 const unsigned* __restrict__ whr, const unsigned* __restrict__ wlr,
                 const float* __restrict__ bias,
                 float* __restrict__ out, int nrows) {
    __shared__ unsigned sAhi[128 * SWH];
    __shared__ unsigned sAlo[128 * SWH];
    __shared__ unsigned sBhi[48 * SWBS];
    __shared__ unsigned sBlo[48 * SWBS];
    __shared__ float    sBn[256];

    int tid  = threadIdx.x;
    int row0 = blockIdx.x * 128;
    int lane = tid & 31;
    int wid  = tid >> 5;
    int qr = lane >> 2, qc = lane & 3;
    int r0w = wid * 16;

    if (tid < 256) sBn[tid] = bnp[tid];

    unsigned baseAhi = (unsigned)__cvta_generic_to_shared(sAhi);
    unsigned baseAlo = (unsigned)__cvta_generic_to_shared(sAlo);
    unsigned baseBhi = (unsigned)__cvta_generic_to_shared(sBhi);
    unsigned baseBlo = (unsigned)__cvta_generic_to_shared(sBlo);
    int lm = lane >> 3, lr = lane & 7;
    unsigned offA = ((( (lm & 1) * 8 + lr) * SWH)  + (lm >> 1) * 4) * 4;
    unsigned offB = ((( (lm >> 1) * 8 + lr) * SWBS) + (lm & 1) * 4) * 4;
    __syncthreads();

    float acc[6][4];
    #pragma unroll
    for (int n = 0; n < 6; n++)
        #pragma unroll
        for (int i = 0; i < 4; i++) acc[n][i] = 0.0f;

    for (int chunk = 0; chunk < 8; chunk++) {
        bool ismean = (chunk < 4);
        int kb2 = (chunk & 3) * 16;
        const unsigned* bh = ismean ? whl : whr;
        const unsigned* bl = ismean ? wll : wlr;

        if (ismean) {
            #pragma unroll
            for (int i = 0; i < 2; i++) {
                int t = i * 256 + tid;
                int r = t >> 2;
                int q = t & 3;
                int row = row0 + r;
                uint4 vh = make_uint4(0,0,0,0), vl = make_uint4(0,0,0,0);
                if (row < nrows) {
                    size_t g = (size_t)row * WPR + kb2 + 4*q;
                    vh = *reinterpret_cast<const uint4*>(meanh + g);
                    vl = *reinterpret_cast<const uint4*>(meanl + g);
                }
                *reinterpret_cast<uint4*>(sAhi + r * SWH + 4*q) = vh;
                *reinterpret_cast<uint4*>(sAlo + r * SWH + 4*q) = vl;
            }
        } else {
            int kbase = (chunk & 3) * 32;
            #pragma unroll
            for (int i = 0; i < 4; i++) {
                int t = i * 256 + tid;
                int r  = t >> 3;
                int c4 = t & 7;
                int row = row0 + r;
                float4 v = make_float4(0.f,0.f,0.f,0.f);
                if (row < nrows) {
                    v = *reinterpret_cast<const float4*>(feat + (size_t)row * HIDF + kbase + 4*c4);
                    int cc = kbase + 4*c4;
                    v.x = fmaxf(fmaf(v.x, sBn[cc+0], sBn[128+cc+0]), 0.f);
                    v.y = fmaxf(fmaf(v.y, sBn[cc+1], sBn[128+cc+1]), 0.f);
                    v.z = fmaxf(fmaf(v.z, sBn[cc+2], sBn[128+cc+2]), 0.f);
                    v.w = fmaxf(fmaf(v.w, sBn[cc+3], sBn[128+cc+3]), 0.f);
                }
                unsigned h[2], l[2];
                split4(v, h, l);
                *reinterpret_cast<uint2*>(sAhi + r * SWH + c4 * 2) = make_uint2(h[0], h[1]);
                *reinterpret_cast<uint2*>(sAlo + r * SWH + c4 * 2) = make_uint2(l[0], l[1]);
            }
        }
        if (tid < 160) {
            int n = tid >> 2;
            int q = tid & 3;
            size_t g = (size_t)n * WPR + kb2 + 4*q;
            *reinterpret_cast<uint4*>(sBhi + n * SWBS + 4*q) =
                *reinterpret_cast<const uint4*>(bh + g);
            *reinterpret_cast<uint4*>(sBlo + n * SWBS + 4*q) =
                *reinterpret_cast<const uint4*>(bl + g);
        }
        __syncthreads();

        #pragma unroll
        for (int s = 0; s < 2; s++) {
            int wb = s * 8;
            unsigned ah[4], al[4];
            unsigned ao = ((r0w * SWH) + wb) * 4;
            ldsm_x4(ah, baseAhi + offA + ao);
            ldsm_x4(al, baseAlo + offA + ao);
            #pragma unroll
            for (int p = 0; p < 3; p++) {
                unsigned bhf[4], blf[4];
                unsigned bo = (((p*16) * SWBS) + wb) * 4;
                ldsm_x4(bhf, baseBhi + offB + bo);
                ldsm_x4(blf, baseBlo + offB + bo);
                MMA_BF16(acc[2*p],   ah[0],ah[1],ah[2],ah[3], bhf[0],bhf[1]);
                MMA_BF16(acc[2*p],   ah[0],ah[1],ah[2],ah[3], blf[0],blf[1]);
                MMA_BF16(acc[2*p],   al[0],al[1],al[2],al[3], bhf[0],bhf[1]);
                MMA_BF16(acc[2*p+1], ah[0],ah[1],ah[2],ah[3], bhf[2],bhf[3]);
                MMA_BF16(acc[2*p+1], ah[0],ah[1],ah[2],ah[3], blf[2],blf[3]);
                MMA_BF16(acc[2*p+1], al[0],al[1],al[2],al[3], bhf[2],bhf[3]);
            }
        }
        __syncthreads();
    }

    int rowa = row0 + r0w + qr;
    int rowb = rowa + 8;
    #pragma unroll
    for (int nt = 0; nt < 5; nt++) {
        int col = nt*8 + 2*qc;
        float b0 = bias[col], b1 = bias[col+1];
        if (rowa < nrows)
            *reinterpret_cast<float2*>(out + (size_t)rowa * OUTF + col) =
                make_float2(acc[nt][0] + b0, acc[nt][1] + b1);
        if (rowb < nrows)
            *reinterpret_cast<float2*>(out + (size_t)rowb * OUTF + col) =
                make_float2(acc[nt][2] + b0, acc[nt][3] + b1);
    }
}

// ---------------- launch ----------------
extern "C" void kernel_launch(void* const* d_in, const int* in_sizes, int n_in,
                              void* d_out, int out_size) {
    const float* x   = (const float*)d_in[0];
    const int*   ei  = (const int*)d_in[1];
    const float* Wl0 = (const float*)d_in[2];
    const float* Wr0 = (const float*)d_in[3];
    const float* Wl1 = (const float*)d_in[4];
    const float* Wr1 = (const float*)d_in[5];
    const float* Wl2 = (const float*)d_in[6];
    const float* Wr2 = (const float*)d_in[7];
    const float* b2  = (const float*)d_in[8];
    const float* g0  = (const float*)d_in[9];
    const float* be0 = (const float*)d_in[10];
    const float* g1  = (const float*)d_in[11];
    const float* be1 = (const float*)d_in[12];
    float* out = (float*)d_out;

    int E = in_sizes[1] / 2;
    int N = in_sizes[0] / HIDF;

    float *h0, *h1, *sums, *bnp0, *bnp1;
    unsigned *meanh, *meanl, *wh, *wl;
    int *rowptr, *cursor, *csr, *bsum;
    cudaGetSymbolAddress((void**)&meanh, g_meanh);
    cudaGetSymbolAddress((void**)&meanl, g_meanl);
    cudaGetSymbolAddress((void**)&h0,    g_h0);
    cudaGetSymbolAddress((void**)&h1,    g_h1);
    cudaGetSymbolAddress((void**)&sums,  g_sums);
    cudaGetSymbolAddress((void**)&bnp0,  g_bnp0);
    cudaGetSymbolAddress((void**)&bnp1,  g_bnp1);
    cudaGetSymbolAddress((void**)&rowptr, g_rowptr);
    cudaGetSymbolAddress((void**)&cursor, g_cursor);
    cudaGetSymbolAddress((void**)&csr,    g_csr);
    cudaGetSymbolAddress((void**)&bsum,   g_bsum);
    cudaGetSymbolAddress((void**)&wh,     g_wh);
    cudaGetSymbolAddress((void**)&wl,     g_wl);

    int np1 = N + 1;
    int nscan = (np1 + 1023) / 1024;
    int tc_blocks = (N + 127) / 128;
    int ga_blocks = (N + 7) / 8;

    // ---- CSR build + weight pre-split ----
    zero_int_kernel<<<(np1 + 255) / 256, 256>>>(rowptr, np1);
    degree_kernel<<<(E + 255) / 256, 256>>>(ei, rowptr, E, N);
    scan1_kernel<<<nscan, 1024>>>(rowptr, bsum, np1);
    scan2_kernel<<<1, 1024>>>(bsum, nscan);
    scan3_kernel<<<nscan, 1024>>>(rowptr, bsum, cursor, np1, N);
    fill_kernel<<<(E + 255) / 256, 256>>>(ei, cursor, csr, E, N);
    zero_f_kernel<<<1, 512>>>(sums, 512);
    splitw_kernel<<<(WTOT + 255) / 256, 256>>>(Wl0, Wr0, Wl1, Wr1, Wl2, Wr2, wh, wl);

    // ---- layer 0 ----
    gather_kernel<<<ga_blocks, 256>>>(x, rowptr, csr, nullptr, meanh, meanl, N);
    gemm_tc128_kernel<<<tc_blocks, 256>>>(meanh, meanl, x, nullptr,
                                          wh + WOFF_L0, wl + WOFF_L0,
                                          wh + WOFF_R0, wl + WOFF_R0,
                                          h0, sums, N);
    bn_finalize_kernel<<<1, 128>>>(sums, g0, be0, bnp0, N);

    // ---- layer 1 ----
    gather_kernel<<<ga_blocks, 256>>>(h0, rowptr, csr, bnp0, meanh, meanl, N);
    gemm_tc128_kernel<<<tc_blocks, 256>>>(meanh, meanl, h0, bnp0,
                                          wh + WOFF_L1, wl + WOFF_L1,
                                          wh + WOFF_R1, wl + WOFF_R1,
                                          h1, sums + 256, N);
    bn_finalize_kernel<<<1, 128>>>(sums + 256, g1, be1, bnp1, N);

    // ---- layer 2 ----
    gather_kernel<<<ga_blocks, 256>>>(h1, rowptr, csr, bnp1, meanh, meanl, N);
    gemm_tc40_kernel<<<tc_blocks, 256>>>(meanh, meanl, h1, bnp1,
                                         wh + WOFF_L2, wl + WOFF_L2,
                                         wh + WOFF_R2, wl + WOFF_R2,
                                         b2, out, N);
}

// round 17
// speedup vs baseline: 1.0115x; 1.0092x over previous
#include <cuda_runtime.h>
#include <cuda_bf16.h>
#include <cstdint>

#define N_NODES 100000
#define E_EDGES 800000
#define HIDF 128
#define OUTF 40
#define BN_EPS 1e-5f
#define WPR 64          // bf16x2 words per feature row (128 bf16)

// ---------------- scratch ----------------
__device__ unsigned g_meanh[(size_t)N_NODES * WPR];
__device__ unsigned g_meanl[(size_t)N_NODES * WPR];
__device__ float g_h0 [(size_t)N_NODES * HIDF];
__device__ float g_h1 [(size_t)N_NODES * HIDF];
__device__ int   g_rowptr[N_NODES + 1];
__device__ int   g_cursor[N_NODES];
__device__ int   g_csr[E_EDGES];
__device__ int   g_bsum[1024];
__device__ float g_sums[512];
__device__ float g_bnp0[256];
__device__ float g_bnp1[256];
#define WOFF_L0 0
#define WOFF_R0 8192
#define WOFF_L1 16384
#define WOFF_R1 24576
#define WOFF_L2 32768
#define WOFF_R2 35328
#define WTOT    37888
__device__ unsigned g_wh[WTOT];
__device__ unsigned g_wl[WTOT];

// ---------------- helpers ----------------
__device__ __forceinline__ unsigned pack_bf16x2(float lo, float hi) {
    unsigned r;
    asm("cvt.rn.bf16x2.f32 %0, %1, %2;" : "=r"(r) : "f"(hi), "f"(lo));
    return r;
}
__device__ __forceinline__ float bf_lo(unsigned u) { return __uint_as_float(u << 16); }
__device__ __forceinline__ float bf_hi(unsigned u) { return __uint_as_float(u & 0xffff0000u); }

__device__ __forceinline__ void split4(float4 v, unsigned* h, unsigned* l) {
    h[0] = pack_bf16x2(v.x, v.y);
    h[1] = pack_bf16x2(v.z, v.w);
    l[0] = pack_bf16x2(v.x - bf_lo(h[0]), v.y - bf_hi(h[0]));
    l[1] = pack_bf16x2(v.z - bf_lo(h[1]), v.w - bf_hi(h[1]));
}

#define MMA_BF16(d, A0,A1,A2,A3, B0,B1) \
    asm volatile("mma.sync.aligned.m16n8k16.row.col.f32.bf16.bf16.f32 " \
        "{%0,%1,%2,%3}, {%4,%5,%6,%7}, {%8,%9}, {%0,%1,%2,%3};" \
        : "+f"((d)[0]), "+f"((d)[1]), "+f"((d)[2]), "+f"((d)[3]) \
        : "r"(A0), "r"(A1), "r"(A2), "r"(A3), "r"(B0), "r"(B1))

__device__ __forceinline__ void ldsm_x4(unsigned* r, unsigned addr) {
    asm volatile("ldmatrix.sync.aligned.m8n8.x4.shared.b16 {%0,%1,%2,%3}, [%4];"
                 : "=r"(r[0]), "=r"(r[1]), "=r"(r[2]), "=r"(r[3]) : "r"(addr));
}

__device__ __forceinline__ void redg_f32(float* p, float v) {
    asm volatile("red.global.add.f32 [%0], %1;" :: "l"(p), "f"(v) : "memory");
}

// ---------------- small utils ----------------
__global__ void zero_int_kernel(int* __restrict__ p, int n) {
    int i = blockIdx.x * blockDim.x + threadIdx.x;
    if (i < n) p[i] = 0;
}
__global__ void zero_f_kernel(float* __restrict__ p, int n) {
    int i = blockIdx.x * blockDim.x + threadIdx.x;
    if (i < n) p[i] = 0.0f;
}

// ---------------- weight pre-split ----------------
__global__ void splitw_kernel(const float* __restrict__ Wl0, const float* __restrict__ Wr0,
                              const float* __restrict__ Wl1, const float* __restrict__ Wr1,
                              const float* __restrict__ Wl2, const float* __restrict__ Wr2,
                              unsigned* __restrict__ wh, unsigned* __restrict__ wl) {
    int i = blockIdx.x * blockDim.x + threadIdx.x;
    if (i >= WTOT) return;
    const float* src; int idx, NC;
    if      (i < WOFF_R0) { src = Wl0; idx = i;            NC = 128; }
    else if (i < WOFF_L1) { src = Wr0; idx = i - WOFF_R0;  NC = 128; }
    else if (i < WOFF_R1) { src = Wl1; idx = i - WOFF_L1;  NC = 128; }
    else if (i < WOFF_L2) { src = Wr1; idx = i - WOFF_R1;  NC = 128; }
    else if (i < WOFF_R2) { src = Wl2; idx = i - WOFF_L2;  NC = OUTF; }
    else                  { src = Wr2; idx = i - WOFF_R2;  NC = OUTF; }
    int n = idx >> 6, kw = idx & 63;
    float v0 = src[(size_t)(2*kw)     * NC + n];
    float v1 = src[(size_t)(2*kw + 1) * NC + n];
    unsigned h = pack_bf16x2(v0, v1);
    unsigned l = pack_bf16x2(v0 - bf_lo(h), v1 - bf_hi(h));
    wh[i] = h; wl[i] = l;
}

// ---------------- CSR build ----------------
__global__ void degree_kernel(const int* __restrict__ ei, int* __restrict__ rowptr,
                              int E, int N) {
    int e = blockIdx.x * blockDim.x + threadIdx.x;
    if (e >= E) return;
    int s = ei[e], d = ei[E + e];
    if ((unsigned)s < (unsigned)N && (unsigned)d < (unsigned)N)
        atomicAdd(&rowptr[d + 1], 1);
}

__global__ void scan1_kernel(int* __restrict__ data, int* __restrict__ bsum, int n) {
    __shared__ int sh[1024];
    int gid = blockIdx.x * 1024 + threadIdx.x;
    int v = (gid < n) ? data[gid] : 0;
    sh[threadIdx.x] = v;
    __syncthreads();
    #pragma unroll
    for (int off = 1; off < 1024; off <<= 1) {
        int t = (threadIdx.x >= off) ? sh[threadIdx.x - off] : 0;
        __syncthreads();
        sh[threadIdx.x] += t;
        __syncthreads();
    }
    if (gid < n) data[gid] = sh[threadIdx.x];
    if (threadIdx.x == 1023) bsum[blockIdx.x] = sh[1023];
}

__global__ void scan2_kernel(int* __restrict__ bsum, int nb) {
    __shared__ int sh[1024];
    int v = (threadIdx.x < nb) ? bsum[threadIdx.x] : 0;
    sh[threadIdx.x] = v;
    __syncthreads();
    #pragma unroll
    for (int off = 1; off < 1024; off <<= 1) {
        int t = (threadIdx.x >= off) ? sh[threadIdx.x - off] : 0;
        __syncthreads();
        sh[threadIdx.x] += t;
        __syncthreads();
    }
    if (threadIdx.x < nb) bsum[threadIdx.x] = sh[threadIdx.x];
}

__global__ void scan3_kernel(int* __restrict__ data, const int* __restrict__ bsum,
                             int* __restrict__ cursor, int n, int N) {
    int gid = blockIdx.x * 1024 + threadIdx.x;
    if (gid >= n) return;
    int add = (blockIdx.x > 0) ? bsum[blockIdx.x - 1] : 0;
    int v = data[gid] + add;
    data[gid] = v;
    if (gid < N) cursor[gid] = v;
}

__global__ void fill_kernel(const int* __restrict__ ei, int* __restrict__ cursor,
                            int* __restrict__ csr, int E, int N) {
    int e = blockIdx.x * blockDim.x + threadIdx.x;
    if (e >= E) return;
    int s = ei[e], d = ei[E + e];
    if ((unsigned)s >= (unsigned)N || (unsigned)d >= (unsigned)N) return;
    int pos = atomicAdd(&cursor[d], 1);
    csr[pos] = s;
}

// ---------------- gather-mean, writes split bf16 hi/lo words ----------------
__global__ void __launch_bounds__(256)
gather_kernel(const float* __restrict__ feat,
              const int* __restrict__ rowptr,
              const int* __restrict__ csr,
              const float* __restrict__ bnp,
              unsigned* __restrict__ meanh,
              unsigned* __restrict__ meanl, int N) {
    int node = blockIdx.x * 8 + (threadIdx.x >> 5);
    if (node >= N) return;
    int c = (threadIdx.x & 31) << 2;

    float4 sc = make_float4(1.f,1.f,1.f,1.f), sh = make_float4(0.f,0.f,0.f,0.f);
    bool bn = (bnp != nullptr);
    if (bn) {
        sc = *reinterpret_cast<const float4*>(bnp + c);
        sh = *reinterpret_cast<const float4*>(bnp + 128 + c);
    }

    int beg = rowptr[node], end = rowptr[node + 1];
    float4 acc = make_float4(0.f,0.f,0.f,0.f);
    int j = beg;
    for (; j + 4 <= end; j += 4) {
        int i0 = csr[j], i1 = csr[j+1], i2 = csr[j+2], i3 = csr[j+3];
        float4 v0 = *reinterpret_cast<const float4*>(feat + (size_t)i0 * HIDF + c);
        float4 v1 = *reinterpret_cast<const float4*>(feat + (size_t)i1 * HIDF + c);
        float4 v2 = *reinterpret_cast<const float4*>(feat + (size_t)i2 * HIDF + c);
        float4 v3 = *reinterpret_cast<const float4*>(feat + (size_t)i3 * HIDF + c);
        if (bn) {
            v0.x=fmaxf(fmaf(v0.x,sc.x,sh.x),0.f); v0.y=fmaxf(fmaf(v0.y,sc.y,sh.y),0.f);
            v0.z=fmaxf(fmaf(v0.z,sc.z,sh.z),0.f); v0.w=fmaxf(fmaf(v0.w,sc.w,sh.w),0.f);
            v1.x=fmaxf(fmaf(v1.x,sc.x,sh.x),0.f); v1.y=fmaxf(fmaf(v1.y,sc.y,sh.y),0.f);
            v1.z=fmaxf(fmaf(v1.z,sc.z,sh.z),0.f); v1.w=fmaxf(fmaf(v1.w,sc.w,sh.w),0.f);
            v2.x=fmaxf(fmaf(v2.x,sc.x,sh.x),0.f); v2.y=fmaxf(fmaf(v2.y,sc.y,sh.y),0.f);
            v2.z=fmaxf(fmaf(v2.z,sc.z,sh.z),0.f); v2.w=fmaxf(fmaf(v2.w,sc.w,sh.w),0.f);
            v3.x=fmaxf(fmaf(v3.x,sc.x,sh.x),0.f); v3.y=fmaxf(fmaf(v3.y,sc.y,sh.y),0.f);
            v3.z=fmaxf(fmaf(v3.z,sc.z,sh.z),0.f); v3.w=fmaxf(fmaf(v3.w,sc.w,sh.w),0.f);
        }
        acc.x += v0.x + v1.x + v2.x + v3.x;
        acc.y += v0.y + v1.y + v2.y + v3.y;
        acc.z += v0.z + v1.z + v2.z + v3.z;
        acc.w += v0.w + v1.w + v2.w + v3.w;
    }
    for (; j < end; j++) {
        int i0 = csr[j];
        float4 v0 = *reinterpret_cast<const float4*>(feat + (size_t)i0 * HIDF + c);
        if (bn) {
            v0.x=fmaxf(fmaf(v0.x,sc.x,sh.x),0.f); v0.y=fmaxf(fmaf(v0.y,sc.y,sh.y),0.f);
            v0.z=fmaxf(fmaf(v0.z,sc.z,sh.z),0.f); v0.w=fmaxf(fmaf(v0.w,sc.w,sh.w),0.f);
        }
        acc.x += v0.x; acc.y += v0.y; acc.z += v0.z; acc.w += v0.w;
    }
    float invd = (end > beg) ? 1.0f / (float)(end - beg) : 0.0f;
    acc.x *= invd; acc.y *= invd; acc.z *= invd; acc.w *= invd;
    unsigned h[2], l[2];
    split4(acc, h, l);
    size_t w = (size_t)node * WPR + (c >> 1);
    *reinterpret_cast<uint2*>(meanh + w) = make_uint2(h[0], h[1]);
    *reinterpret_cast<uint2*>(meanl + w) = make_uint2(l[0], l[1]);
}

// ======== bf16 3x-split TC GEMM, ldmatrix fragments, register-prefetch pipeline =====
#define SWH  20
#define SWBS 20

__global__ void __launch_bounds__(256, 2)
gemm_tc128_kernel(const unsigned* __restrict__ meanh,
                  const unsigned* __restrict__ meanl,
                  const float* __restrict__ feat,
                  const float* __restrict__ bnp,
                  const unsigned* __restrict__ whl, const unsigned* __restrict__ wll,
                  const unsigned* __restrict__ whr, const unsigned* __restrict__ wlr,
                  float* __restrict__ out,
                  float* __restrict__ stats,
                  int nrows) {
    __shared__ unsigned sAhi[128 * SWH];
    __shared__ unsigned sAlo[128 * SWH];
    __shared__ unsigned sBhi[128 * SWBS];
    __shared__ unsigned sBlo[128 * SWBS];
    __shared__ float    sBn[256];

    int tid  = threadIdx.x;
    int row0 = blockIdx.x * 128;
    int lane = tid & 31;
    int wid  = tid >> 5;
    int qr = lane >> 2, qc = lane & 3;
    int r0w = (wid & 3) * 32;
    int n0w = (wid >> 2) * 64;
    bool hasbn = (bnp != nullptr);

    if (hasbn && tid < 256) sBn[tid] = bnp[tid];

    unsigned baseAhi = (unsigned)__cvta_generic_to_shared(sAhi);
    unsigned baseAlo = (unsigned)__cvta_generic_to_shared(sAlo);
    unsigned baseBhi = (unsigned)__cvta_generic_to_shared(sBhi);
    unsigned baseBlo = (unsigned)__cvta_generic_to_shared(sBlo);
    int lm = lane >> 3, lr = lane & 7;
    unsigned offA = ((( (lm & 1) * 8 + lr) * SWH)  + (lm >> 1) * 4) * 4;
    unsigned offB = ((( (lm >> 1) * 8 + lr) * SWBS) + (lm & 1) * 4) * 4;

    // per-thread staging indices
    int ar_m = tid >> 2, aq_m = tid & 3;             // mean path: 2 tasks (rows ar_m, ar_m+64)
    int ar_f = tid >> 3, ac_f = tid & 7;             // feat path: 4 tasks (rows +0,32,64,96)
    int bn_i = tid >> 2, bq_i = tid & 3;             // B path: 2 tasks (n, n+64)
    __syncthreads();

    float acc[2][8][4];
    #pragma unroll
    for (int m = 0; m < 2; m++)
        #pragma unroll
        for (int n = 0; n < 8; n++)
            #pragma unroll
            for (int i = 0; i < 4; i++) acc[m][n][i] = 0.0f;

    uint4 pa[4], pb[4];

    // ---- issue loads for a chunk into registers ----
    #define ISSUE(chunk) do {                                                     \
        bool ismean = ((chunk) < 4);                                              \
        int kb2 = ((chunk) & 3) * 16;                                             \
        const unsigned* bh = ismean ? whl : whr;                                  \
        const unsigned* bl = ismean ? wll : wlr;                                  \
        if (ismean) {                                                             \
            _Pragma("unroll")                                                     \
            for (int i = 0; i < 2; i++) {                                         \
                int r = ar_m + i * 64;                                            \
                int row = row0 + r;                                               \
                uint4 vh = make_uint4(0,0,0,0), vl = make_uint4(0,0,0,0);         \
                if (row < nrows) {                                                \
                    size_t g = (size_t)row * WPR + kb2 + 4*aq_m;                  \
                    vh = *reinterpret_cast<const uint4*>(meanh + g);              \
                    vl = *reinterpret_cast<const uint4*>(meanl + g);              \
                }                                                                 \
                pa[2*i] = vh; pa[2*i+1] = vl;                                     \
            }                                                                     \
        } else {                                                                  \
            int kbase = ((chunk) & 3) * 32;                                       \
            _Pragma("unroll")                                                     \
            for (int i = 0; i < 4; i++) {                                         \
                int row = row0 + ar_f + i * 32;                                   \
                uint4 v = make_uint4(0,0,0,0);                                    \
                if (row < nrows)                                                  \
                    v = *reinterpret_cast<const uint4*>(                          \
                        feat + (size_t)row * HIDF + kbase + 4*ac_f);              \
                pa[i] = v;                                                        \
            }                                                                     \
        }                                                                         \
        _Pragma("unroll")                                                         \
        for (int i = 0; i < 2; i++) {                                             \
            int n = bn_i + i * 64;                                                \
            size_t g = (size_t)n * WPR + kb2 + 4*bq_i;                            \
            pb[2*i]   = *reinterpret_cast<const uint4*>(bh + g);                  \
            pb[2*i+1] = *reinterpret_cast<const uint4*>(bl + g);                  \
        }                                                                         \
    } while (0)

    // ---- store registers into smem (with transform on feat path) ----
    #define STORE(chunk) do {                                                     \
        bool ismean = ((chunk) < 4);                                              \
        if (ismean) {                                                             \
            _Pragma("unroll")                                                     \
            for (int i = 0; i < 2; i++) {                                         \
                int r = ar_m + i * 64;                                            \
                *reinterpret_cast<uint4*>(sAhi + r * SWH + 4*aq_m) = pa[2*i];     \
                *reinterpret_cast<uint4*>(sAlo + r * SWH + 4*aq_m) = pa[2*i+1];   \
            }                                                                     \
        } else {                                                                  \
            int kbase = ((chunk) & 3) * 32;                                       \
            _Pragma("unroll")                                                     \
            for (int i = 0; i < 4; i++) {                                         \
                int r = ar_f + i * 32;                                            \
                float4 v = make_float4(__uint_as_float(pa[i].x),                  \
                                       __uint_as_float(pa[i].y),                  \
                                       __uint_as_float(pa[i].z),                  \
                                       __uint_as_float(pa[i].w));                 \
                if (hasbn) {                                                      \
                    int cc = kbase + 4*ac_f;                                      \
                    v.x = fmaxf(fmaf(v.x, sBn[cc+0], sBn[128+cc+0]), 0.f);        \
                    v.y = fmaxf(fmaf(v.y, sBn[cc+1], sBn[128+cc+1]), 0.f);        \
                    v.z = fmaxf(fmaf(v.z, sBn[cc+2], sBn[128+cc+2]), 0.f);        \
                    v.w = fmaxf(fmaf(v.w, sBn[cc+3], sBn[128+cc+3]), 0.f);        \
                }                                                                 \
                unsigned h[2], l[2];                                              \
                split4(v, h, l);                                                  \
                *reinterpret_cast<uint2*>(sAhi + r * SWH + ac_f * 2) =            \
                    make_uint2(h[0], h[1]);                                       \
                *reinterpret_cast<uint2*>(sAlo + r * SWH + ac_f * 2) =            \
                    make_uint2(l[0], l[1]);                                       \
            }                                                                     \
        }                                                                         \
        _Pragma("unroll")                                                         \
        for (int i = 0; i < 2; i++) {                                             \
            int n = bn_i + i * 64;                                                \
            *reinterpret_cast<uint4*>(sBhi + n * SWBS + 4*bq_i) = pb[2*i];        \
            *reinterpret_cast<uint4*>(sBlo + n * SWBS + 4*bq_i) = pb[2*i+1];      \
        }                                                                         \
    } while (0)

    ISSUE(0);
    for (int chunk = 0; chunk < 8; chunk++) {
        STORE(chunk);
        __syncthreads();
        if (chunk < 7) {
            // issue next chunk's loads; consumed only at next STORE -> overlap with mma
            switch (chunk + 1) {
                case 1: ISSUE(1); break;
                case 2: ISSUE(2); break;
                case 3: ISSUE(3); break;
                case 4: ISSUE(4); break;
                case 5: ISSUE(5); break;
                case 6: ISSUE(6); break;
                case 7: ISSUE(7); break;
            }
        }
        #pragma unroll
        for (int s = 0; s < 2; s++) {
            int wb = s * 8;
            unsigned ah[2][4], al[2][4];
            #pragma unroll
            for (int mt = 0; mt < 2; mt++) {
                unsigned ao = (((r0w + mt*16) * SWH) + wb) * 4;
                ldsm_x4(ah[mt], baseAhi + offA + ao);
                ldsm_x4(al[mt], baseAlo + offA + ao);
            }
            #pragma unroll
            for (int p = 0; p < 4; p++) {
                unsigned bhf[4], blf[4];
                unsigned bo = (((n0w + p*16) * SWBS) + wb) * 4;
                ldsm_x4(bhf, baseBhi + offB + bo);
                ldsm_x4(blf, baseBlo + offB + bo);
                #pragma unroll
                for (int mt = 0; mt < 2; mt++) {
                    MMA_BF16(acc[mt][2*p],   ah[mt][0],ah[mt][1],ah[mt][2],ah[mt][3], bhf[0],bhf[1]);
                    MMA_BF16(acc[mt][2*p],   ah[mt][0],ah[mt][1],ah[mt][2],ah[mt][3], blf[0],blf[1]);
                    MMA_BF16(acc[mt][2*p],   al[mt][0],al[mt][1],al[mt][2],al[mt][3], bhf[0],bhf[1]);
                    MMA_BF16(acc[mt][2*p+1], ah[mt][0],ah[mt][1],ah[mt][2],ah[mt][3], bhf[2],bhf[3]);
                    MMA_BF16(acc[mt][2*p+1], ah[mt][0],ah[mt][1],ah[mt][2],ah[mt][3], blf[2],blf[3]);
                    MMA_BF16(acc[mt][2*p+1], al[mt][0],al[mt][1],al[mt][2],al[mt][3], bhf[2],bhf[3]);
                }
            }
        }
        __syncthreads();
    }
    #undef ISSUE
    #undef STORE

    // write out
    #pragma unroll
    for (int mt = 0; mt < 2; mt++) {
        int rowa = row0 + r0w + mt*16 + qr;
        int rowb = rowa + 8;
        #pragma unroll
        for (int nt = 0; nt < 8; nt++) {
            int col = n0w + nt*8 + 2*qc;
            if (rowa < nrows)
                *reinterpret_cast<float2*>(out + (size_t)rowa * HIDF + col) =
                    make_float2(acc[mt][nt][0], acc[mt][nt][1]);
            if (rowb < nrows)
                *reinterpret_cast<float2*>(out + (size_t)rowb * HIDF + col) =
                    make_float2(acc[mt][nt][2], acc[mt][nt][3]);
        }
    }

    // fused BN statistics
    #pragma unroll
    for (int nt = 0; nt < 8; nt++) {
        #pragma unroll
        for (int p = 0; p < 2; p++) {
            float v0 = acc[0][nt][p],   v1 = acc[0][nt][p+2];
            float v2 = acc[1][nt][p],   v3 = acc[1][nt][p+2];
            float s = v0 + v1 + v2 + v3;
            float q = v0*v0 + v1*v1 + v2*v2 + v3*v3;
            #pragma unroll
            for (int off = 4; off < 32; off <<= 1) {
                s += __shfl_xor_sync(0xffffffff, s, off);
                q += __shfl_xor_sync(0xffffffff, q, off);
            }
            if (qr == 0) {
                int col = n0w + nt*8 + 2*qc + p;
                redg_f32(stats + col, s);
                redg_f32(stats + 128 + col, q);
            }
        }
    }
}

// ---- bn finalize ----
__global__ void bn_finalize_kernel(const float* __restrict__ stats,
                                   const float* __restrict__ g,
                                   const float* __restrict__ be,
                                   float* __restrict__ bnp, int nrows) {
    int c = threadIdx.x;
    float invN = 1.0f / (float)nrows;
    float mu  = stats[c] * invN;
    float var = stats[128 + c] * invN - mu * mu;
    float sc  = g[c] * rsqrtf(var + BN_EPS);
    bnp[c]       = sc;
    bnp[128 + c] = be[c] - mu * sc;
}

// ---- NC=40 variant (unchanged pipeline shape; small kernel) ----
__global__ void __launch_bounds__(256)
gemm_tc40_kernel(const unsigned* __restrict__ meanh,
                 const unsigned* __restrict__ meanl,
                 const float* __restrict__ feat,
                 const float* __restrict__ bnp,
                 const unsigned* __restrict__ whl, const unsigned* __restrict__ wll,
                 const unsigned* __restrict__ whr, const unsigned* __restrict__ wlr,
                 const float* __restrict__ bias,
                 float* __restrict__ out, int nrows) {
    __shared__ unsigned sAhi[128 * SWH];
    __shared__ unsigned sAlo[128 * SWH];
    __shared__ unsigned sBhi[48 * SWBS];
    __shared__ unsigned sBlo[48 * SWBS];
    __shared__ float    sBn[256];

    int tid  = threadIdx.x;
    int row0 = blockIdx.x * 128;
    int lane = tid & 31;
    int wid  = tid >> 5;
    int qr = lane >> 2, qc = lane & 3;
    int r0w = wid * 16;

    if (tid < 256) sBn[tid] = bnp[tid];

    unsigned baseAhi = (unsigned)__cvta_generic_to_shared(sAhi);
    unsigned baseAlo = (unsigned)__cvta_generic_to_shared(sAlo);
    unsigned baseBhi = (unsigned)__cvta_generic_to_shared(sBhi);
    unsigned baseBlo = (unsigned)__cvta_generic_to_shared(sBlo);
    int lm = lane >> 3, lr = lane & 7;
    unsigned offA = ((( (lm & 1) * 8 + lr) * SWH)  + (lm >> 1) * 4) * 4;
    unsigned offB = ((( (lm >> 1) * 8 + lr) * SWBS) + (lm & 1) * 4) * 4;
    __syncthreads();

    float acc[6][4];
    #pragma unroll
    for (int n = 0; n < 6; n++)
        #pragma unroll
        for (int i = 0; i < 4; i++) acc[n][i] = 0.0f;

    for (int chunk = 0; chunk < 8; chunk++) {
        bool ismean = (chunk < 4);
        int kb2 = (chunk & 3) * 16;
        const unsigned* bh = ismean ? whl : whr;
        const unsigned* bl = ismean ? wll : wlr;

        if (ismean) {
            #pragma unroll
            for (int i = 0; i < 2; i++) {
                int t = i * 256 + tid;
                int r = t >> 2;
                int q = t & 3;
                int row = row0 + r;
                uint4 vh = make_uint4(0,0,0,0), vl = make_uint4(0,0,0,0);
                if (row < nrows) {
                    size_t g = (size_t)row * WPR + kb2 + 4*q;
                    vh = *reinterpret_cast<const uint4*>(meanh + g);
                    vl = *reinterpret_cast<const uint4*>(meanl + g);
                }
                *reinterpret_cast<uint4*>(sAhi + r * SWH + 4*q) = vh;
                *reinterpret_cast<uint4*>(sAlo + r * SWH + 4*q) = vl;
            }
        } else {
            int kbase = (chunk & 3) * 32;
            #pragma unroll
            for (int i = 0; i < 4; i++) {
                int t = i * 256 + tid;
                int r  = t >> 3;
                int c4 = t & 7;
                int row = row0 + r;
                float4 v = make_float4(0.f,0.f,0.f,0.f);
                if (row < nrows) {
                    v = *reinterpret_cast<const float4*>(feat + (size_t)row * HIDF + kbase + 4*c4);
                    int cc = kbase + 4*c4;
                    v.x = fmaxf(fmaf(v.x, sBn[cc+0], sBn[128+cc+0]), 0.f);
                    v.y = fmaxf(fmaf(v.y, sBn[cc+1], sBn[128+cc+1]), 0.f);
                    v.z = fmaxf(fmaf(v.z, sBn[cc+2], sBn[128+cc+2]), 0.f);
                    v.w = fmaxf(fmaf(v.w, sBn[cc+3], sBn[128+cc+3]), 0.f);
                }
                unsigned h[2], l[2];
                split4(v, h, l);
                *reinterpret_cast<uint2*>(sAhi + r * SWH + c4 * 2) = make_uint2(h[0], h[1]);
                *reinterpret_cast<uint2*>(sAlo + r * SWH + c4 * 2) = make_uint2(l[0], l[1]);
            }
        }
        if (tid < 160) {
            int n = tid >> 2;
            int q = tid & 3;
            size_t g = (size_t)n * WPR + kb2 + 4*q;
            *reinterpret_cast<uint4*>(sBhi + n * SWBS + 4*q) =
                *reinterpret_cast<const uint4*>(bh + g);
            *reinterpret_cast<uint4*>(sBlo + n * SWBS + 4*q) =
                *reinterpret_cast<const uint4*>(bl + g);
        }
        __syncthreads();

        #pragma unroll
        for (int s = 0; s < 2; s++) {
            int wb = s * 8;
            unsigned ah[4], al[4];
            unsigned ao = ((r0w * SWH) + wb) * 4;
            ldsm_x4(ah, baseAhi + offA + ao);
            ldsm_x4(al, baseAlo + offA + ao);
            #pragma unroll
            for (int p = 0; p < 3; p++) {
                unsigned bhf[4], blf[4];
                unsigned bo = (((p*16) * SWBS) + wb) * 4;
                ldsm_x4(bhf, baseBhi + offB + bo);
                ldsm_x4(blf, baseBlo + offB + bo);
                MMA_BF16(acc[2*p],   ah[0],ah[1],ah[2],ah[3], bhf[0],bhf[1]);
                MMA_BF16(acc[2*p],   ah[0],ah[1],ah[2],ah[3], blf[0],blf[1]);
                MMA_BF16(acc[2*p],   al[0],al[1],al[2],al[3], bhf[0],bhf[1]);
                MMA_BF16(acc[2*p+1], ah[0],ah[1],ah[2],ah[3], bhf[2],bhf[3]);
                MMA_BF16(acc[2*p+1], ah[0],ah[1],ah[2],ah[3], blf[2],blf[3]);
                MMA_BF16(acc[2*p+1], al[0],al[1],al[2],al[3], bhf[2],bhf[3]);
            }
        }
        __syncthreads();
    }

    int rowa = row0 + r0w + qr;
    int rowb = rowa + 8;
    #pragma unroll
    for (int nt = 0; nt < 5; nt++) {
        int col = nt*8 + 2*qc;
        float b0 = bias[col], b1 = bias[col+1];
        if (rowa < nrows)
            *reinterpret_cast<float2*>(out + (size_t)rowa * OUTF + col) =
                make_float2(acc[nt][0] + b0, acc[nt][1] + b1);
        if (rowb < nrows)
            *reinterpret_cast<float2*>(out + (size_t)rowb * OUTF + col) =
                make_float2(acc[nt][2] + b0, acc[nt][3] + b1);
    }
}

// ---------------- launch ----------------
extern "C" void kernel_launch(void* const* d_in, const int* in_sizes, int n_in,
                              void* d_out, int out_size) {
    const float* x   = (const float*)d_in[0];
    const int*   ei  = (const int*)d_in[1];
    const float* Wl0 = (const float*)d_in[2];
    const float* Wr0 = (const float*)d_in[3];
    const float* Wl1 = (const float*)d_in[4];
    const float* Wr1 = (const float*)d_in[5];
    const float* Wl2 = (const float*)d_in[6];
    const float* Wr2 = (const float*)d_in[7];
    const float* b2  = (const float*)d_in[8];
    const float* g0  = (const float*)d_in[9];
    const float* be0 = (const float*)d_in[10];
    const float* g1  = (const float*)d_in[11];
    const float* be1 = (const float*)d_in[12];
    float* out = (float*)d_out;

    int E = in_sizes[1] / 2;
    int N = in_sizes[0] / HIDF;

    float *h0, *h1, *sums, *bnp0, *bnp1;
    unsigned *meanh, *meanl, *wh, *wl;
    int *rowptr, *cursor, *csr, *bsum;
    cudaGetSymbolAddress((void**)&meanh, g_meanh);
    cudaGetSymbolAddress((void**)&meanl, g_meanl);
    cudaGetSymbolAddress((void**)&h0,    g_h0);
    cudaGetSymbolAddress((void**)&h1,    g_h1);
    cudaGetSymbolAddress((void**)&sums,  g_sums);
    cudaGetSymbolAddress((void**)&bnp0,  g_bnp0);
    cudaGetSymbolAddress((void**)&bnp1,  g_bnp1);
    cudaGetSymbolAddress((void**)&rowptr, g_rowptr);
    cudaGetSymbolAddress((void**)&cursor, g_cursor);
    cudaGetSymbolAddress((void**)&csr,    g_csr);
    cudaGetSymbolAddress((void**)&bsum,   g_bsum);
    cudaGetSymbolAddress((void**)&wh,     g_wh);
    cudaGetSymbolAddress((void**)&wl,     g_wl);

    int np1 = N + 1;
    int nscan = (np1 + 1023) / 1024;
    int tc_blocks = (N + 127) / 128;
    int ga_blocks = (N + 7) / 8;

    // ---- CSR build + weight pre-split ----
    zero_int_kernel<<<(np1 + 255) / 256, 256>>>(rowptr, np1);
    degree_kernel<<<(E + 255) / 256, 256>>>(ei, rowptr, E, N);
    scan1_kernel<<<nscan, 1024>>>(rowptr, bsum, np1);
    scan2_kernel<<<1, 1024>>>(bsum, nscan);
    scan3_kernel<<<nscan, 1024>>>(rowptr, bsum, cursor, np1, N);
    fill_kernel<<<(E + 255) / 256, 256>>>(ei, cursor, csr, E, N);
    zero_f_kernel<<<1, 512>>>(sums, 512);
    splitw_kernel<<<(WTOT + 255) / 256, 256>>>(Wl0, Wr0, Wl1, Wr1, Wl2, Wr2, wh, wl);

    // ---- layer 0 ----
    gather_kernel<<<ga_blocks, 256>>>(x, rowptr, csr, nullptr, meanh, meanl, N);
    gemm_tc128_kernel<<<tc_blocks, 256>>>(meanh, meanl, x, nullptr,
                                          wh + WOFF_L0, wl + WOFF_L0,
                                          wh + WOFF_R0, wl + WOFF_R0,
                                          h0, sums, N);
    bn_finalize_kernel<<<1, 128>>>(sums, g0, be0, bnp0, N);

    // ---- layer 1 ----
    gather_kernel<<<ga_blocks, 256>>>(h0, rowptr, csr, bnp0, meanh, meanl, N);
    gemm_tc128_kernel<<<tc_blocks, 256>>>(meanh, meanl, h0, bnp0,
                                          wh + WOFF_L1, wl + WOFF_L1,
                                          wh + WOFF_R1, wl + WOFF_R1,
                                          h1, sums + 256, N);
    bn_finalize_kernel<<<1, 128>>>(sums + 256, g1, be1, bnp1, N);

    // ---- layer 2 ----
    gather_kernel<<<ga_blocks, 256>>>(h1, rowptr, csr, bnp1, meanh, meanl, N);
    gemm_tc40_kernel<<<tc_blocks, 256>>>(meanh, meanl, h1, bnp1,
                                         wh + WOFF_L2, wl + WOFF_L2,
                                         wh + WOFF_R2, wl + WOFF_R2,
                                         b2, out, N);
}